// round 12
// baseline (speedup 1.0000x reference)
#include <cuda_runtime.h>
#include <cuda_fp16.h>
#include <cstdint>
#include <math.h>

#define B_     16
#define N_     196
#define E_     512
#define H_     8
#define HD_    64
#define C_     2048
#define HDC_   256
#define FN_    784
#define BN_    3136
#define NE_    100352
#define FNE_   401408
#define BNE_   1605632
#define SCHZ_  38416
#define ATTZ_  153664
#define LP_    200

// ---------------- scratch ----------------
__device__ __align__(128) __half h_cx  [4*BN_*E_];
__device__ __align__(128) __half h_cxT [4*B_*E_*LP_];
__device__ __align__(128) __half h_ec  [BN_*C_];
__device__ __align__(128) __half h_qkv [3LL*BN_*C_];
__device__ __align__(128) __half h_vcT [B_*C_*LP_];
__device__ __align__(128) float  g_sch [B_*H_*N_*N_];
__device__ __align__(128) __half h_sch [B_*H_*N_*LP_];
__device__ __align__(128) __half h_t   [BN_*C_];
__device__ __align__(128) __half h_that[BN_*C_];
__device__ __align__(128) __half h_kvsT[B_*E_*FN_];
__device__ __align__(128) __half h_KV  [2*B_*FN_*E_];
__device__ __align__(128) __half h_VT  [B_*E_*FN_];
__device__ __align__(128) __half h_Q   [4*BN_*E_];
__device__ __align__(128) __half h_attnL[512u*196*784];   // half logits
__device__ __align__(128) __half h_attn [512u*196*784];   // half probs
__device__ __align__(128) float  g_parts[512*14*2];
__device__ __align__(128) float  g_rstd[512];
__device__ __align__(128) __half h_cm  [4LL*BNE_];
__device__ __align__(128) __half h_ctx0[BNE_];
__device__ __align__(128) float  g_embA[4LL*BNE_];
__device__ __align__(128) float  g_h   [4*BN_*E_];
__device__ __align__(128) __half h_xln [4*BN_*E_];
__device__ __align__(128) __half h_x1  [4*BN_*2048];
__device__ __align__(128) __half h_qwT [4*N_*LP_];
__device__ __align__(128) __half h_kvwT[2*FN_*FN_];
__device__ __align__(128) __half h_Wqkv[3LL*C_*C_];
__device__ __align__(128) __half h_WoT [C_*C_];
__device__ __align__(128) __half h_outwT[4*E_*E_];
__device__ __align__(128) __half h_fc1wT[4*2048*E_];
__device__ __align__(128) __half h_fc2wT[4*E_*2048];

// ---------------- helpers ----------------
__device__ __forceinline__ uint32_t smem_u32(const void* p) {
    uint32_t a;
    asm("{ .reg .u64 t; cvta.to.shared.u64 t, %1; cvt.u32.u64 %0, t; }" : "=r"(a) : "l"(p));
    return a;
}
__device__ __forceinline__ void mma_f16(float* d, const uint32_t* a, const uint32_t* b) {
    asm volatile(
        "mma.sync.aligned.m16n8k16.row.col.f32.f16.f16.f32 "
        "{%0,%1,%2,%3}, {%4,%5,%6,%7}, {%8,%9}, {%0,%1,%2,%3};"
        : "+f"(d[0]), "+f"(d[1]), "+f"(d[2]), "+f"(d[3])
        : "r"(a[0]), "r"(a[1]), "r"(a[2]), "r"(a[3]), "r"(b[0]), "r"(b[1]));
}
__device__ __forceinline__ float gelu_f(float v) {
    return 0.5f * v * (1.f + erff(v * 0.70710678118654752f));
}
__device__ __forceinline__ void cpa16(uint32_t dst, const __half* src, int bytes) {
    asm volatile("cp.async.ca.shared.global [%0], [%1], 16, %2;"
                 :: "r"(dst), "l"(src), "r"(bytes) : "memory");
}
#define CP_COMMIT() asm volatile("cp.async.commit_group;" ::: "memory")
#define CP_WAIT1()  asm volatile("cp.async.wait_group 1;" ::: "memory")

// ---------------- reductions ----------------
__device__ __forceinline__ float block_sum(float v, float* sh) {
    int tid = threadIdx.x;
    #pragma unroll
    for (int o = 16; o > 0; o >>= 1) v += __shfl_down_sync(0xffffffffu, v, o);
    if ((tid & 31) == 0) sh[tid >> 5] = v;
    __syncthreads();
    if (tid < 32) {
        float t = (tid < (int)(blockDim.x >> 5)) ? sh[tid] : 0.f;
        #pragma unroll
        for (int o = 16; o > 0; o >>= 1) t += __shfl_down_sync(0xffffffffu, t, o);
        if (tid == 0) sh[0] = t;
    }
    __syncthreads();
    float r = sh[0];
    __syncthreads();
    return r;
}
__device__ __forceinline__ float block_max(float v, float* sh) {
    int tid = threadIdx.x;
    #pragma unroll
    for (int o = 16; o > 0; o >>= 1) v = fmaxf(v, __shfl_down_sync(0xffffffffu, v, o));
    if ((tid & 31) == 0) sh[tid >> 5] = v;
    __syncthreads();
    if (tid < 32) {
        float t = (tid < (int)(blockDim.x >> 5)) ? sh[tid] : -INFINITY;
        #pragma unroll
        for (int o = 16; o > 0; o >>= 1) t = fmaxf(t, __shfl_down_sync(0xffffffffu, t, o));
        if (tid == 0) sh[0] = t;
    }
    __syncthreads();
    float r = sh[0];
    __syncthreads();
    return r;
}

// ---------------- LN ----------------
__global__ void __launch_bounds__(256) ln_fused_kernel(
    const float* __restrict__ e1, const float* __restrict__ e2,
    const float* __restrict__ e3, const float* __restrict__ e4,
    const float* __restrict__ lag, const float* __restrict__ lab,
    const float* __restrict__ lcg, const float* __restrict__ lcb,
    __half* __restrict__ cx, __half* __restrict__ ec)
{
    __shared__ float sh[32];
    int token = blockIdx.x;
    int tid = threadIdx.x;
    const float* es[4] = {e1, e2, e3, e4};
    float x[4][2], mg[4], rg[4];
    float stot = 0.f, sstot = 0.f;
    #pragma unroll
    for (int g = 0; g < 4; g++) {
        const float* p = es[g] + (long long)token * E_;
        x[g][0] = p[tid]; x[g][1] = p[tid + 256];
        float s  = block_sum(x[g][0] + x[g][1], sh);
        float ss = block_sum(x[g][0]*x[g][0] + x[g][1]*x[g][1], sh);
        float m = s * (1.f/512.f);
        float v = ss * (1.f/512.f) - m*m;
        mg[g] = m; rg[g] = rsqrtf(v + 1e-6f);
        stot += s; sstot += ss;
    }
    float m = stot * (1.f/2048.f);
    float r = rsqrtf(sstot * (1.f/2048.f) - m*m + 1e-6f);
    #pragma unroll
    for (int g = 0; g < 4; g++) {
        #pragma unroll
        for (int j = 0; j < 2; j++) {
            int e = tid + j*256;
            float xv = x[g][j];
            cx[((long long)g*BN_ + token)*E_ + e] =
                __float2half_rn((xv - mg[g]) * rg[g] * lag[g*E_+e] + lab[g*E_+e]);
            ec[(long long)token*C_ + g*E_ + e] =
                __float2half_rn((xv - m) * r * lcg[g*E_+e] + lcb[g*E_+e]);
        }
    }
}

__global__ void __launch_bounds__(256) ln_rows_kernel(
    const float* __restrict__ X, const float* __restrict__ gamma,
    const float* __restrict__ beta, __half* __restrict__ Y, int rowsPerG)
{
    __shared__ float sh[32];
    long long row = blockIdx.x;
    int tid = threadIdx.x;
    int g = (int)(row / rowsPerG);
    const float* p = X + row * E_;
    float x0 = p[tid], x1 = p[tid+256];
    float s  = block_sum(x0 + x1, sh);
    float ss = block_sum(x0*x0 + x1*x1, sh);
    float m = s * (1.f/512.f);
    float r = rsqrtf(ss * (1.f/512.f) - m*m + 1e-6f);
    __half* q = Y + row * E_;
    q[tid]     = __float2half_rn((x0 - m) * r * gamma[g*E_+tid]     + beta[g*E_+tid]);
    q[tid+256] = __float2half_rn((x1 - m) * r * gamma[g*E_+tid+256] + beta[g*E_+tid+256]);
}

// ---------------- rstd from per-CTA partials ----------------
__global__ void rstd_parts(const float* __restrict__ parts, float* __restrict__ rstd, int nparts) {
    int z = blockIdx.x;
    int t = threadIdx.x;
    float s = 0.f, q = 0.f;
    if (t < nparts) { s = parts[(z*nparts+t)*2]; q = parts[(z*nparts+t)*2+1]; }
    #pragma unroll
    for (int o = 16; o > 0; o >>= 1) {
        s += __shfl_down_sync(0xffffffffu, s, o);
        q += __shfl_down_sync(0xffffffffu, q, o);
    }
    if (t == 0) {
        float m = s * (1.f/(float)ATTZ_);
        rstd[z] = rsqrtf(q * (1.f/(float)ATTZ_) - m*m + 1e-5f);
    }
}

// ---------------- softmax: TI logits -> half probs ----------------
template<int NIT, bool PERZ, typename TI>
__global__ void __launch_bounds__(256) softmax_fix(
    const TI* __restrict__ S, __half* __restrict__ O,
    int cols, int ldo, int rowsPerZ,
    const float* __restrict__ rstd, float scale)
{
    __shared__ float sh[32];
    long long row = blockIdx.x;
    const TI* p = S + row * cols;
    __half* q = O + row * ldo;
    float sc = PERZ ? rstd[(int)(row / rowsPerZ)] : scale;
    int tid = threadIdx.x;
    float vals[NIT];
    float mx = -INFINITY;
    #pragma unroll
    for (int it = 0; it < NIT; it++) {
        int i = tid + it*256;
        float t = (i < cols) ? (float)p[i]*sc : -INFINITY;
        vals[it] = t;
        mx = fmaxf(mx, t);
    }
    mx = block_max(mx, sh);
    float s = 0.f;
    #pragma unroll
    for (int it = 0; it < NIT; it++) {
        float e = expf(vals[it] - mx);
        vals[it] = e;
        s += e;
    }
    s = block_sum(s, sh);
    float inv = 1.f / s;
    #pragma unroll
    for (int it = 0; it < NIT; it++) {
        int i = tid + it*256;
        if (i < cols) q[i] = __float2half_rn(vals[it] * inv);
    }
}

// ---------------- tiled transpose ----------------
template<typename TI, typename TO>
__global__ void transpose_t(const TI* __restrict__ in, TO* __restrict__ out,
                            int R, int Cc, int ldo, long long zi, long long zo)
{
    __shared__ float t[32][33];
    const TI* ip = in + (long long)blockIdx.z * zi;
    TO* op = out + (long long)blockIdx.z * zo;
    int c0 = blockIdx.x*32, r0 = blockIdx.y*32;
    int x = threadIdx.x, y = threadIdx.y;
    #pragma unroll
    for (int j = 0; j < 32; j += 8) {
        int r = r0 + y + j, c = c0 + x;
        if (r < R && c < Cc) t[y+j][x] = (float)ip[(long long)r*Cc + c];
    }
    __syncthreads();
    #pragma unroll
    for (int j = 0; j < 32; j += 8) {
        int c = c0 + y + j, r = r0 + x;
        if (r < R && c < Cc) op[(long long)c*ldo + r] = (TO)t[x][y+j];
    }
}

// batched square transpose fp32->half: up to 4 independent (in,out) pairs, z selects
__global__ void transpose4_sq(const float* __restrict__ p0, const float* __restrict__ p1,
                              const float* __restrict__ p2, const float* __restrict__ p3,
                              __half* __restrict__ o0, __half* __restrict__ o1,
                              __half* __restrict__ o2, __half* __restrict__ o3, int D)
{
    __shared__ float t[32][33];
    int zi = blockIdx.z;
    const float* ip = (zi == 0) ? p0 : (zi == 1) ? p1 : (zi == 2) ? p2 : p3;
    __half* op = (zi == 0) ? o0 : (zi == 1) ? o1 : (zi == 2) ? o2 : o3;
    int c0 = blockIdx.x*32, r0 = blockIdx.y*32;
    int x = threadIdx.x, y = threadIdx.y;
    #pragma unroll
    for (int j = 0; j < 32; j += 8) {
        int r = r0 + y + j, c = c0 + x;
        if (r < D && c < D) t[y+j][x] = ip[(long long)r*D + c];
    }
    __syncthreads();
    #pragma unroll
    for (int j = 0; j < 32; j += 8) {
        int c = c0 + y + j, r = r0 + x;
        if (r < D && c < D) op[(long long)c*D + r] = (__half)t[x][y+j];
    }
}

__global__ void kvsT_kernel(const __half* __restrict__ that, __half* __restrict__ kvsT)
{
    __shared__ __half t[32][34];
    int g = blockIdx.z & 3, b = blockIdx.z >> 2;
    int n0 = blockIdx.y*32, e0 = blockIdx.x*32;
    const __half* in = that + (long long)b*N_*C_ + g*E_;
    __half* out = kvsT + (long long)b*E_*FN_ + g*N_;
    int x = threadIdx.x, y = threadIdx.y;
    #pragma unroll
    for (int j = 0; j < 32; j += 8) {
        int n = n0 + y + j;
        if (n < N_) t[y+j][x] = in[(long long)n*C_ + e0 + x];
    }
    __syncthreads();
    #pragma unroll
    for (int j = 0; j < 32; j += 8) {
        int n = n0 + x;
        if (n < N_) out[(long long)(e0+y+j)*FN_ + n] = t[x][y+j];
    }
}

__global__ void merge0_kernel(const __half* __restrict__ cm, __half* __restrict__ ctx0) {
    int idx = blockIdx.x * blockDim.x + threadIdx.x;
    if (idx >= BN_*E_) return;
    int b = idx / NE_;
    int rem = idx % NE_;
    int n = rem / E_;
    int e = rem % E_;
    int h = e >> 6, d = e & 63;
    ctx0[idx] = cm[((long long)(b*H_ + h)*N_ + n)*HD_ + d];
}

__global__ void copy_half8(const __half* __restrict__ src, __half* __restrict__ dst, int n8) {
    int i = blockIdx.x * blockDim.x + threadIdx.x;
    if (i < n8) ((uint4*)dst)[i] = ((const uint4*)src)[i];
}

__global__ void pack_emb(const float* __restrict__ e1, const float* __restrict__ e2,
                         const float* __restrict__ e3, const float* __restrict__ e4,
                         float* __restrict__ out) {
    const float* es[4] = {e1, e2, e3, e4};
    int g = blockIdx.y;
    int i = blockIdx.x * blockDim.x + threadIdx.x;
    if (i < BNE_) out[(long long)g*BNE_ + i] = es[g][i];
}

// ---------------- fp16 mma.sync GEMM (R7 mainloop) + optional fused stats ----------------
__device__ __forceinline__ void epi_store(
    void* __restrict__ Cv, const float* __restrict__ bias, const float* __restrict__ res,
    int ldc, int row, int gc, int M, int act, int outHalf, float alpha, float c0, float c1)
{
    if (row >= M) return;
    float2 v = make_float2(c0*alpha, c1*alpha);
    if (bias) { v.x += bias[gc]; v.y += bias[gc+1]; }
    if (act)  { v.x = gelu_f(v.x); v.y = gelu_f(v.y); }
    if (res)  { float2 rr = *(const float2*)(res + (long long)row*ldc + gc);
                v.x += rr.x; v.y += rr.y; }
    if (outHalf) {
        *(__half2*)((__half*)Cv + (long long)row*ldc + gc) = __floats2half2_rn(v.x, v.y);
    } else {
        *(float2*)((float*)Cv + (long long)row*ldc + gc) = v;
    }
}

template<int TM, int TN, int WM, int WN>
__global__ void __launch_bounds__(256, 1) gemm_h(
    int M, int Ncol, int K,
    const __half* __restrict__ A, int lda,
    const __half* __restrict__ B, int ldb,
    void* __restrict__ Cv, int ldc,
    const float* __restrict__ bias,
    const float* __restrict__ res,
    int act, int outHalf, float alpha,
    int D0, int D1,
    long long sA0, long long sA1, long long sA2,
    long long sB0, long long sB1, long long sB2,
    long long sC0, long long sC1, long long sC2,
    long long sBias0, long long sR0,
    float* __restrict__ sout)
{
    constexpr int WMS = TM / WM;
    constexpr int MI  = WM / 16;
    constexpr int NJ  = WN / 8;
    constexpr int ABUFW = TM * 32;
    constexpr int BBUFW = TN * 32;
    constexpr int ASLOT = (TM*2 + 255) / 256;
    constexpr int BSLOT = (TN*2 + 255) / 256;

    long long z = blockIdx.z;
    int z0 = (int)(z % D0); long long t = z / D0;
    int z1 = (int)(t % D1); int z2 = (int)(t / D1);
    A += z0*sA0 + z1*sA1 + z2*sA2;
    B += z0*sB0 + z1*sB1 + z2*sB2;
    long long coff = z0*sC0 + z1*sC1 + z2*sC2;
    Cv = outHalf ? (void*)((__half*)Cv + coff) : (void*)((float*)Cv + coff);
    if (bias) bias += z0*sBias0;
    if (res)  res  += z0*sR0;

    extern __shared__ uint32_t smw[];
    uint32_t* As = smw;
    uint32_t* Bs = smw + 2*ABUFW;

    int tid = threadIdx.x;
    int lane = tid & 31;
    int wid = tid >> 5;
    int warp_m = wid % WMS;
    int warp_n = wid / WMS;
    int row0 = blockIdx.y * TM;
    int col0 = blockIdx.x * TN;

    float acc[MI][NJ][4];
    #pragma unroll
    for (int i = 0; i < MI; i++)
        #pragma unroll
        for (int j = 0; j < NJ; j++)
            #pragma unroll
            for (int q = 0; q < 4; q++) acc[i][j][q] = 0.f;

    const __half* aPtr[ASLOT]; uint32_t aOff[ASLOT][4]; int aKh[ASLOT]; bool aV[ASLOT];
    const __half* bPtr[BSLOT]; uint32_t bOff[BSLOT][4]; int bKh[BSLOT]; bool bV[BSLOT];
    #pragma unroll
    for (int i = 0; i < ASLOT; i++) {
        int sidx = tid + i*256;
        bool inA = sidx < TM*2;
        int r = inA ? (sidx >> 1) : 0;
        int khw = (sidx & 1) * 16;
        aKh[i] = (sidx & 1) * 32;
        bool val = inA && (row0 + r) < M;
        aV[i] = val;
        aPtr[i] = A + (long long)(val ? row0 + r : 0) * lda;
        int sw = (r & 7) << 2;
        #pragma unroll
        for (int j = 0; j < 4; j++)
            aOff[i][j] = (uint32_t)((r*32 + ((khw + j*4) ^ sw)) << 2);
    }
    #pragma unroll
    for (int i = 0; i < BSLOT; i++) {
        int sidx = tid + i*256;
        bool inB = sidx < TN*2;
        int r = inB ? (sidx >> 1) : 0;
        int khw = (sidx & 1) * 16;
        bKh[i] = (sidx & 1) * 32;
        bool val = inB && (col0 + r) < Ncol;
        bV[i] = val;
        bPtr[i] = B + (long long)(val ? col0 + r : 0) * ldb;
        int sw = (r & 7) << 2;
        #pragma unroll
        for (int j = 0; j < 4; j++)
            bOff[i][j] = (uint32_t)((r*32 + ((khw + j*4) ^ sw)) << 2);
    }

    uint32_t aSm = smem_u32(As);
    uint32_t bSm = smem_u32(Bs);
    int KT = (K + 63) >> 6;
    int lr = lane >> 2;
    int lc = lane & 3;

    // prologue -> buffer 0
    #pragma unroll
    for (int i = 0; i < ASLOT; i++) {
        if ((ASLOT > 1) && (tid + i*256 >= TM*2)) continue;
        #pragma unroll
        for (int j = 0; j < 4; j++) {
            int gk = aKh[i] + j*8;
            int nb = (K - gk) * 2; nb = nb < 0 ? 0 : (nb > 16 ? 16 : nb);
            int ba = aV[i] ? nb : 0;
            cpa16(aSm + aOff[i][j], aPtr[i] + (ba ? gk : 0), ba);
        }
    }
    #pragma unroll
    for (int i = 0; i < BSLOT; i++) {
        if (tid + i*256 >= TN*2) continue;
        #pragma unroll
        for (int j = 0; j < 4; j++) {
            int gk = bKh[i] + j*8;
            int nb = (K - gk) * 2; nb = nb < 0 ? 0 : (nb > 16 ? 16 : nb);
            int bb = bV[i] ? nb : 0;
            cpa16(bSm + bOff[i][j], bPtr[i] + (bb ? gk : 0), bb);
        }
    }
    CP_COMMIT();

    for (int kt = 0; kt < KT; kt++) {
        int p = kt & 1;
        __syncthreads();
        if (kt + 1 < KT) {
            uint32_t aBo = (uint32_t)((1 - p) * ABUFW * 4);
            uint32_t bBo = (uint32_t)((1 - p) * BBUFW * 4);
            int k0 = (kt+1)*64;
            #pragma unroll
            for (int i = 0; i < ASLOT; i++) {
                if ((ASLOT > 1) && (tid + i*256 >= TM*2)) continue;
                #pragma unroll
                for (int j = 0; j < 4; j++) {
                    int gk = k0 + aKh[i] + j*8;
                    int nb = (K - gk) * 2; nb = nb < 0 ? 0 : (nb > 16 ? 16 : nb);
                    int ba = aV[i] ? nb : 0;
                    cpa16(aSm + aBo + aOff[i][j], aPtr[i] + (ba ? gk : 0), ba);
                }
            }
            #pragma unroll
            for (int i = 0; i < BSLOT; i++) {
                if (tid + i*256 >= TN*2) continue;
                #pragma unroll
                for (int j = 0; j < 4; j++) {
                    int gk = k0 + bKh[i] + j*8;
                    int nb = (K - gk) * 2; nb = nb < 0 ? 0 : (nb > 16 ? 16 : nb);
                    int bb = bV[i] ? nb : 0;
                    cpa16(bSm + bBo + bOff[i][j], bPtr[i] + (bb ? gk : 0), bb);
                }
            }
        }
        CP_COMMIT();
        CP_WAIT1();
        __syncthreads();

        const uint32_t* Ab = As + p*ABUFW;
        const uint32_t* Bb = Bs + p*BBUFW;
        #pragma unroll
        for (int ks = 0; ks < 4; ks++) {
            int w0 = ks*8 + lc;
            int w1 = w0 + 4;
            uint32_t af[MI][4], bf[NJ][2];
            #pragma unroll
            for (int i = 0; i < MI; i++) {
                int m = warp_m*WM + i*16 + lr;
                int s = (m & 7) << 2;
                af[i][0] = Ab[m*32 + (w0 ^ s)];
                af[i][1] = Ab[(m+8)*32 + (w0 ^ s)];
                af[i][2] = Ab[m*32 + (w1 ^ s)];
                af[i][3] = Ab[(m+8)*32 + (w1 ^ s)];
            }
            #pragma unroll
            for (int j = 0; j < NJ; j++) {
                int n = warp_n*WN + j*8 + lr;
                int s = (n & 7) << 2;
                bf[j][0] = Bb[n*32 + (w0 ^ s)];
                bf[j][1] = Bb[n*32 + (w1 ^ s)];
            }
            #pragma unroll
            for (int i = 0; i < MI; i++)
                #pragma unroll
                for (int j = 0; j < NJ; j++)
                    mma_f16(acc[i][j], af[i], bf[j]);
        }
    }

    #pragma unroll
    for (int i = 0; i < MI; i++) {
        int gr = row0 + warp_m*WM + i*16 + lr;
        #pragma unroll
        for (int j = 0; j < NJ; j++) {
            int gc = col0 + warp_n*WN + j*8 + lc*2;
            if (gc >= Ncol) continue;
            epi_store(Cv, bias, res, ldc, gr,   gc, M, act, outHalf, alpha, acc[i][j][0], acc[i][j][1]);
            epi_store(Cv, bias, res, ldc, gr+8, gc, M, act, outHalf, alpha, acc[i][j][2], acc[i][j][3]);
        }
    }

    if (sout) {
        float s = 0.f, q = 0.f;
        #pragma unroll
        for (int i = 0; i < MI; i++)
            #pragma unroll
            for (int j = 0; j < NJ; j++)
                #pragma unroll
                for (int qq = 0; qq < 4; qq++) {
                    float v = acc[i][j][qq];
                    s += v; q += v*v;
                }
        #pragma unroll
        for (int o = 16; o > 0; o >>= 1) {
            s += __shfl_down_sync(0xffffffffu, s, o);
            q += __shfl_down_sync(0xffffffffu, q, o);
        }
        float* shf = (float*)smw;
        __syncthreads();
        if (lane == 0) { shf[wid] = s; shf[8 + wid] = q; }
        __syncthreads();
        if (tid == 0) {
            float ts = 0.f, tq = 0.f;
            #pragma unroll
            for (int w = 0; w < 8; w++) { ts += shf[w]; tq += shf[8 + w]; }
            long long cid = (long long)blockIdx.z * (gridDim.x * gridDim.y)
                          + blockIdx.y * gridDim.x + blockIdx.x;
            sout[cid*2]   = ts;
            sout[cid*2+1] = tq;
        }
    }
}

// ---------------- host ----------------
static void* symaddr(const void* sym) {
    void* p = nullptr;
    cudaGetSymbolAddress(&p, sym);
    return p;
}

#define G1 gemm_h<128,128,64,32>
#define G2 gemm_h<128,256,64,64>
#define G3 gemm_h<128,64,32,32>
#define SM1 65536
#define SM2 98304
#define SM3 49152

extern "C" void kernel_launch(void* const* d_in, const int* in_sizes, int n_in,
                              void* d_out, int out_size) {
    const float* emb[4] = {(const float*)d_in[0], (const float*)d_in[1],
                           (const float*)d_in[2], (const float*)d_in[3]};
    const float* lag  = (const float*)d_in[4];
    const float* lab  = (const float*)d_in[5];
    const float* lcg  = (const float*)d_in[6];
    const float* lcb  = (const float*)d_in[7];
    const float* Wq   = (const float*)d_in[8];
    const float* Wk   = (const float*)d_in[9];
    const float* Wv   = (const float*)d_in[10];
    const float* Wo   = (const float*)d_in[11];
    const float* q_w  = (const float*)d_in[12];
    const float* k_w  = (const float*)d_in[13];
    const float* v_w  = (const float*)d_in[14];
    const float* outw = (const float*)d_in[15];
    const float* lfg  = (const float*)d_in[16];
    const float* lfb  = (const float*)d_in[17];
    const float* fc1w = (const float*)d_in[18];
    const float* fc1b = (const float*)d_in[19];
    const float* fc2w = (const float*)d_in[20];
    const float* fc2b = (const float*)d_in[21];
    float* out = (float*)d_out;

    cudaFuncSetAttribute(G1, cudaFuncAttributeMaxDynamicSharedMemorySize, SM1);
    cudaFuncSetAttribute(G2, cudaFuncAttributeMaxDynamicSharedMemorySize, SM2);
    cudaFuncSetAttribute(G3, cudaFuncAttributeMaxDynamicSharedMemorySize, SM3);

    __half* cx   = (__half*)symaddr(h_cx);   __half* cxT  = (__half*)symaddr(h_cxT);
    __half* ec   = (__half*)symaddr(h_ec);
    __half* qkv  = (__half*)symaddr(h_qkv);  __half* vcT  = (__half*)symaddr(h_vcT);
    float*  sch  = (float*)symaddr(g_sch);   __half* schh = (__half*)symaddr(h_sch);
    __half* tbuf = (__half*)symaddr(h_t);    __half* that = (__half*)symaddr(h_that);
    __half* kvsT = (__half*)symaddr(h_kvsT);
    __half* KV   = (__half*)symaddr(h_KV);   __half* VT   = (__half*)symaddr(h_VT);
    __half* Qb   = (__half*)symaddr(h_Q);
    __half* attnL= (__half*)symaddr(h_attnL);__half* attnh= (__half*)symaddr(h_attn);
    float*  parts= (float*)symaddr(g_parts); float*  rstdp= (float*)symaddr(g_rstd);
    __half* cm   = (__half*)symaddr(h_cm);   __half* ctx0 = (__half*)symaddr(h_ctx0);
    float*  embA = (float*)symaddr(g_embA);
    float*  hbuf = (float*)symaddr(g_h);     __half* xln  = (__half*)symaddr(h_xln);
    __half* x1   = (__half*)symaddr(h_x1);
    __half* qwT  = (__half*)symaddr(h_qwT);  __half* kvwT = (__half*)symaddr(h_kvwT);
    __half* Wqkv = (__half*)symaddr(h_Wqkv); __half* WoT  = (__half*)symaddr(h_WoT);
    __half* outwT= (__half*)symaddr(h_outwT);
    __half* fc1wT= (__half*)symaddr(h_fc1wT);__half* fc2wT= (__half*)symaddr(h_fc2wT);

    const long long Z = 0;
    dim3 tb(32, 8);

    // 1. fused LayerNorms + emb pack
    ln_fused_kernel<<<BN_, 256>>>(emb[0], emb[1], emb[2], emb[3], lag, lab, lcg, lcb, cx, ec);
    pack_emb<<<dim3((BNE_+255)/256, 4), 256>>>(emb[0], emb[1], emb[2], emb[3], embA);

    // 2. weight transposes — batched big squares
    transpose4_sq<<<dim3(64,64,4), tb>>>(Wq, Wk, Wv, Wo,
                                         Wqkv, Wqkv + (long long)C_*C_, Wqkv + 2LL*C_*C_, WoT, C_);
    transpose4_sq<<<dim3(25,25,2), tb>>>(k_w, v_w, k_w, k_w,
                                         kvwT, kvwT + (long long)FN_*FN_, kvwT, kvwT, FN_);
    transpose_t<float,__half><<<dim3(7,7,4),   tb>>>(q_w, qwT, N_, N_, LP_, (long long)N_*N_, (long long)N_*LP_);
    transpose_t<float,__half><<<dim3(16,16,4), tb>>>(outw, outwT, E_, E_, E_, (long long)E_*E_, (long long)E_*E_);
    transpose_t<float,__half><<<dim3(64,16,4), tb>>>(fc1w, fc1wT, E_, 2048, E_, (long long)E_*2048, (long long)2048*E_);
    transpose_t<float,__half><<<dim3(16,64,4), tb>>>(fc2w, fc2wT, 2048, E_, 2048, (long long)2048*E_, (long long)E_*2048);
    transpose_t<__half,__half><<<dim3(16,7,64), tb>>>(cx, cxT, N_, E_, LP_, (long long)NE_, (long long)E_*LP_);

    // 3. channel projections merged QKV (G2, 600 CTAs)
    {
        dim3 g(8, 25, 3);
        G2<<<g,256,SM2>>>(BN_, C_, C_, ec, C_, Wqkv, C_, qkv, C_, nullptr, nullptr, 0, 1, 1.f,
                          3, 1,
                          Z, Z, Z,
                          (long long)C_*C_, Z, Z,
                          (long long)BN_*C_, Z, Z,
                          Z, Z, nullptr);
    }
    transpose_t<__half,__half><<<dim3(64,7,16), tb>>>(qkv + 2LL*BN_*C_, vcT, N_, C_, LP_,
                                                      (long long)N_*C_, (long long)C_*LP_);

    // 4. channel scores per (h,b): fp32 logits (kept fp32 — small tensor)
    {
        dim3 g(2, 2, B_*H_);
        G1<<<g,256,SM1>>>(N_, N_, HDC_, qkv, C_, qkv + (long long)BN_*C_, C_, sch, N_,
                          nullptr, nullptr, 0, 0, 0.0625f,
                          H_, B_,
                          256LL, (long long)N_*C_, Z,
                          256LL, (long long)N_*C_, Z,
                          (long long)SCHZ_, (long long)H_*SCHZ_, Z,
                          Z, Z, nullptr);
    }
    // 5. channel softmax -> half probs
    softmax_fix<1,false,float><<<B_*H_*N_, 256>>>(sch, schh, N_, LP_, 1, nullptr, 1.f);

    // 6. T = s @ v per (h,b)
    {
        dim3 g(1, 2, B_*H_);
        G2<<<g,256,SM2>>>(N_, HDC_, N_, schh, LP_, vcT, LP_, tbuf, C_, nullptr, nullptr, 0, 1, 1.f,
                          H_, B_,
                          (long long)N_*LP_, (long long)H_*N_*LP_, Z,
                          (long long)256*LP_, (long long)C_*LP_, Z,
                          256LL, (long long)N_*C_, Z,
                          Z, Z, nullptr);
    }
    // 7. T_hat = T @ Wo (G2, 200 CTAs)
    {
        dim3 g(8, 25, 1);
        G2<<<g,256,SM2>>>(BN_, C_, C_, tbuf, C_, WoT, C_, that, C_, nullptr, nullptr, 0, 1, 1.f,
                          1,1, Z,Z,Z, Z,Z,Z, Z,Z,Z, Z,Z, nullptr);
    }
    // 8. fused KV_S reshape + transpose
    kvsT_kernel<<<dim3(16, 7, 64), tb>>>(that, kvsT);

    // 9. K/V token-mix merged (G2)
    {
        dim3 g(2, 7, 2*B_);
        G2<<<g,256,SM2>>>(FN_, E_, FN_, kvwT, FN_, kvsT, FN_, KV, E_, nullptr, nullptr, 0, 1, 1.f,
                          2, B_,
                          (long long)FN_*FN_, Z, Z,
                          Z, (long long)E_*FN_, Z,
                          (long long)B_*FNE_, (long long)FNE_, Z,
                          Z, Z, nullptr);
    }
    transpose_t<__half,__half><<<dim3(16,25,16), tb>>>(KV + (long long)B_*FNE_, VT, FN_, E_, FN_,
                                                       (long long)FNE_, (long long)E_*FN_);

    // 10. Q token-mix per (b,g)
    {
        dim3 g(2, 2, 4*B_);
        G2<<<g,256,SM2>>>(N_, E_, N_, qwT, LP_, cxT, LP_, Qb, E_, nullptr, nullptr, 0, 1, 1.f,
                          B_, 4,
                          Z, (long long)N_*LP_, Z,
                          (long long)E_*LP_, (long long)B_*E_*LP_, Z,
                          (long long)NE_, (long long)BNE_, Z,
                          Z, Z, nullptr);
    }
    // 11. spatial logits per (h,b,g): HALF logits + fused fp32 stats partials
    {
        dim3 g(7, 2, 512);
        G1<<<g,256,SM1>>>(N_, FN_, HD_, Qb, E_, KV, E_, attnL, FN_, nullptr, nullptr, 0, 1, 1.f,
                          H_, B_,
                          64LL, (long long)NE_,  (long long)BNE_,
                          64LL, (long long)FNE_, Z,
                          (long long)ATTZ_, (long long)H_*ATTZ_, (long long)B_*H_*ATTZ_,
                          Z, Z, parts);
    }
    // 12-13. rstd + normalized softmax (half logits in, half probs out)
    rstd_parts<<<512, 32>>>(parts, rstdp, 14);
    softmax_fix<4,true,__half><<<512*N_, 256>>>(attnL, attnh, FN_, FN_, N_, rstdp, 1.f);

    // 14. ctx = p @ Vh per (h,b,g) -> cm
    {
        dim3 g(1, 2, 512);
        G3<<<g,256,SM3>>>(N_, HD_, FN_, attnh, FN_, VT, FN_, cm, HD_, nullptr, nullptr, 0, 1, 1.f,
                          H_, B_,
                          (long long)ATTZ_, (long long)H_*ATTZ_, (long long)B_*H_*ATTZ_,
                          (long long)HD_*FN_, (long long)E_*FN_, Z,
                          (long long)N_*HD_, (long long)H_*N_*HD_, (long long)BNE_,
                          Z, Z, nullptr);
    }
    // 15. branch-0 head permute -> slot 0
    merge0_kernel<<<(BN_*E_ + 255)/256, 256>>>(cm, ctx0);
    copy_half8<<<(BNE_/8 + 255)/256, 256>>>(ctx0, cm, BNE_/8);

    // 16. out projection + residual-1 merged over g (G2)
    {
        dim3 g(2, 25, 4);
        G2<<<g,256,SM2>>>(BN_, E_, E_, cm, E_, outwT, E_, hbuf, E_,
                          nullptr, embA, 0, 0, 1.f,
                          4, 1,
                          (long long)BNE_, Z, Z,
                          (long long)E_*E_, Z, Z,
                          (long long)BNE_, Z, Z,
                          Z, (long long)BNE_, nullptr);
    }
    // 17. FFN LayerNorm
    ln_rows_kernel<<<4*BN_, 256>>>(hbuf, lfg, lfb, xln, BN_);

    // 18. fc1 + bias + GELU per g (G2, 800 CTAs)
    {
        dim3 g(8, 25, 4);
        G2<<<g,256,SM2>>>(BN_, 4*E_, E_, xln, E_, fc1wT, E_, x1, 4*E_,
                          fc1b, nullptr, 1, 1, 1.f,
                          4, 1,
                          (long long)BNE_, Z, Z,
                          (long long)2048*E_, Z, Z,
                          (long long)BN_*2048, Z, Z,
                          (long long)2048, Z, nullptr);
    }
    // 19. fc2 + bias + residual-2 -> out (G2)
    {
        dim3 g(2, 25, 4);
        G2<<<g,256,SM2>>>(BN_, E_, 4*E_, x1, 4*E_, fc2wT, 4*E_, out, E_,
                          fc2b, hbuf, 0, 0, 1.f,
                          4, 1,
                          (long long)BN_*2048, Z, Z,
                          (long long)E_*2048, Z, Z,
                          (long long)BNE_, Z, Z,
                          (long long)E_, (long long)BNE_, nullptr);
    }
}

// round 13
// speedup vs baseline: 1.0681x; 1.0681x over previous
#include <cuda_runtime.h>
#include <cuda_fp16.h>
#include <cstdint>
#include <math.h>

#define B_     16
#define N_     196
#define E_     512
#define H_     8
#define HD_    64
#define C_     2048
#define HDC_   256
#define FN_    784
#define BN_    3136
#define NE_    100352
#define FNE_   401408
#define BNE_   1605632
#define SCHZ_  38416
#define ATTZ_  153664
#define LP_    200

// ---------------- scratch ----------------
__device__ __align__(128) __half h_cx  [4*BN_*E_];
__device__ __align__(128) __half h_cxT [4*B_*E_*LP_];
__device__ __align__(128) __half h_ec  [BN_*C_];
__device__ __align__(128) __half h_qkv [3LL*BN_*C_];
__device__ __align__(128) __half h_vcT [B_*C_*LP_];
__device__ __align__(128) float  g_sch [B_*H_*N_*N_];
__device__ __align__(128) __half h_sch [B_*H_*N_*LP_];
__device__ __align__(128) __half h_t   [BN_*C_];
__device__ __align__(128) __half h_that[BN_*C_];
__device__ __align__(128) __half h_kvsT[B_*E_*FN_];
__device__ __align__(128) __half h_KV  [2*B_*FN_*E_];
__device__ __align__(128) __half h_VT  [B_*E_*FN_];
__device__ __align__(128) __half h_Q   [4*BN_*E_];
__device__ __align__(128) __half h_attnL[512u*196*784];   // half logits
__device__ __align__(128) __half h_attn [512u*196*784];   // half probs
__device__ __align__(128) float  g_parts[512*14*2];
__device__ __align__(128) float  g_rstd[512];
__device__ __align__(128) __half h_cm  [4LL*BNE_];
__device__ __align__(128) __half h_ctx0[BNE_];
__device__ __align__(128) float  g_embA[4LL*BNE_];
__device__ __align__(128) float  g_h   [4*BN_*E_];
__device__ __align__(128) __half h_xln [4*BN_*E_];
__device__ __align__(128) __half h_x1  [4*BN_*2048];
__device__ __align__(128) __half h_qwT [4*N_*LP_];
__device__ __align__(128) __half h_kvwT[2*FN_*FN_];
__device__ __align__(128) __half h_Wqkv[3LL*C_*C_];
__device__ __align__(128) __half h_WoT [C_*C_];
__device__ __align__(128) __half h_outwT[4*E_*E_];
__device__ __align__(128) __half h_fc1wT[4*2048*E_];
__device__ __align__(128) __half h_fc2wT[4*E_*2048];

// ---------------- helpers ----------------
__device__ __forceinline__ uint32_t smem_u32(const void* p) {
    uint32_t a;
    asm("{ .reg .u64 t; cvta.to.shared.u64 t, %1; cvt.u32.u64 %0, t; }" : "=r"(a) : "l"(p));
    return a;
}
__device__ __forceinline__ void mma_f16(float* d, const uint32_t* a, const uint32_t* b) {
    asm volatile(
        "mma.sync.aligned.m16n8k16.row.col.f32.f16.f16.f32 "
        "{%0,%1,%2,%3}, {%4,%5,%6,%7}, {%8,%9}, {%0,%1,%2,%3};"
        : "+f"(d[0]), "+f"(d[1]), "+f"(d[2]), "+f"(d[3])
        : "r"(a[0]), "r"(a[1]), "r"(a[2]), "r"(a[3]), "r"(b[0]), "r"(b[1]));
}
__device__ __forceinline__ float gelu_f(float v) {
    return 0.5f * v * (1.f + erff(v * 0.70710678118654752f));
}
__device__ __forceinline__ void cpa16(uint32_t dst, const __half* src, int bytes) {
    asm volatile("cp.async.ca.shared.global [%0], [%1], 16, %2;"
                 :: "r"(dst), "l"(src), "r"(bytes) : "memory");
}
#define CP_COMMIT() asm volatile("cp.async.commit_group;" ::: "memory")
#define CP_WAIT1()  asm volatile("cp.async.wait_group 1;" ::: "memory")

// ---------------- reductions ----------------
__device__ __forceinline__ float block_sum(float v, float* sh) {
    int tid = threadIdx.x;
    #pragma unroll
    for (int o = 16; o > 0; o >>= 1) v += __shfl_down_sync(0xffffffffu, v, o);
    if ((tid & 31) == 0) sh[tid >> 5] = v;
    __syncthreads();
    if (tid < 32) {
        float t = (tid < (int)(blockDim.x >> 5)) ? sh[tid] : 0.f;
        #pragma unroll
        for (int o = 16; o > 0; o >>= 1) t += __shfl_down_sync(0xffffffffu, t, o);
        if (tid == 0) sh[0] = t;
    }
    __syncthreads();
    float r = sh[0];
    __syncthreads();
    return r;
}
__device__ __forceinline__ float block_max(float v, float* sh) {
    int tid = threadIdx.x;
    #pragma unroll
    for (int o = 16; o > 0; o >>= 1) v = fmaxf(v, __shfl_down_sync(0xffffffffu, v, o));
    if ((tid & 31) == 0) sh[tid >> 5] = v;
    __syncthreads();
    if (tid < 32) {
        float t = (tid < (int)(blockDim.x >> 5)) ? sh[tid] : -INFINITY;
        #pragma unroll
        for (int o = 16; o > 0; o >>= 1) t = fmaxf(t, __shfl_down_sync(0xffffffffu, t, o));
        if (tid == 0) sh[0] = t;
    }
    __syncthreads();
    float r = sh[0];
    __syncthreads();
    return r;
}

// ---------------- LN ----------------
__global__ void __launch_bounds__(256) ln_fused_kernel(
    const float* __restrict__ e1, const float* __restrict__ e2,
    const float* __restrict__ e3, const float* __restrict__ e4,
    const float* __restrict__ lag, const float* __restrict__ lab,
    const float* __restrict__ lcg, const float* __restrict__ lcb,
    __half* __restrict__ cx, __half* __restrict__ ec)
{
    __shared__ float sh[32];
    int token = blockIdx.x;
    int tid = threadIdx.x;
    const float* es[4] = {e1, e2, e3, e4};
    float x[4][2], mg[4], rg[4];
    float stot = 0.f, sstot = 0.f;
    #pragma unroll
    for (int g = 0; g < 4; g++) {
        const float* p = es[g] + (long long)token * E_;
        x[g][0] = p[tid]; x[g][1] = p[tid + 256];
        float s  = block_sum(x[g][0] + x[g][1], sh);
        float ss = block_sum(x[g][0]*x[g][0] + x[g][1]*x[g][1], sh);
        float m = s * (1.f/512.f);
        float v = ss * (1.f/512.f) - m*m;
        mg[g] = m; rg[g] = rsqrtf(v + 1e-6f);
        stot += s; sstot += ss;
    }
    float m = stot * (1.f/2048.f);
    float r = rsqrtf(sstot * (1.f/2048.f) - m*m + 1e-6f);
    #pragma unroll
    for (int g = 0; g < 4; g++) {
        #pragma unroll
        for (int j = 0; j < 2; j++) {
            int e = tid + j*256;
            float xv = x[g][j];
            cx[((long long)g*BN_ + token)*E_ + e] =
                __float2half_rn((xv - mg[g]) * rg[g] * lag[g*E_+e] + lab[g*E_+e]);
            ec[(long long)token*C_ + g*E_ + e] =
                __float2half_rn((xv - m) * r * lcg[g*E_+e] + lcb[g*E_+e]);
        }
    }
}

__global__ void __launch_bounds__(256) ln_rows_kernel(
    const float* __restrict__ X, const float* __restrict__ gamma,
    const float* __restrict__ beta, __half* __restrict__ Y, int rowsPerG)
{
    __shared__ float sh[32];
    long long row = blockIdx.x;
    int tid = threadIdx.x;
    int g = (int)(row / rowsPerG);
    const float* p = X + row * E_;
    float x0 = p[tid], x1 = p[tid+256];
    float s  = block_sum(x0 + x1, sh);
    float ss = block_sum(x0*x0 + x1*x1, sh);
    float m = s * (1.f/512.f);
    float r = rsqrtf(ss * (1.f/512.f) - m*m + 1e-6f);
    __half* q = Y + row * E_;
    q[tid]     = __float2half_rn((x0 - m) * r * gamma[g*E_+tid]     + beta[g*E_+tid]);
    q[tid+256] = __float2half_rn((x1 - m) * r * gamma[g*E_+tid+256] + beta[g*E_+tid+256]);
}

// ---------------- rstd from per-CTA partials ----------------
__global__ void rstd_parts(const float* __restrict__ parts, float* __restrict__ rstd, int nparts) {
    int z = blockIdx.x;
    int t = threadIdx.x;
    float s = 0.f, q = 0.f;
    if (t < nparts) { s = parts[(z*nparts+t)*2]; q = parts[(z*nparts+t)*2+1]; }
    #pragma unroll
    for (int o = 16; o > 0; o >>= 1) {
        s += __shfl_down_sync(0xffffffffu, s, o);
        q += __shfl_down_sync(0xffffffffu, q, o);
    }
    if (t == 0) {
        float m = s * (1.f/(float)ATTZ_);
        rstd[z] = rsqrtf(q * (1.f/(float)ATTZ_) - m*m + 1e-5f);
    }
}

// ---------------- softmax: TI logits -> half probs ----------------
template<int NIT, bool PERZ, typename TI>
__global__ void __launch_bounds__(256) softmax_fix(
    const TI* __restrict__ S, __half* __restrict__ O,
    int cols, int ldo, int rowsPerZ,
    const float* __restrict__ rstd, float scale)
{
    __shared__ float sh[32];
    long long row = blockIdx.x;
    const TI* p = S + row * cols;
    __half* q = O + row * ldo;
    float sc = PERZ ? rstd[(int)(row / rowsPerZ)] : scale;
    int tid = threadIdx.x;
    float vals[NIT];
    float mx = -INFINITY;
    #pragma unroll
    for (int it = 0; it < NIT; it++) {
        int i = tid + it*256;
        float t = (i < cols) ? (float)p[i]*sc : -INFINITY;
        vals[it] = t;
        mx = fmaxf(mx, t);
    }
    mx = block_max(mx, sh);
    float s = 0.f;
    #pragma unroll
    for (int it = 0; it < NIT; it++) {
        float e = expf(vals[it] - mx);
        vals[it] = e;
        s += e;
    }
    s = block_sum(s, sh);
    float inv = 1.f / s;
    #pragma unroll
    for (int it = 0; it < NIT; it++) {
        int i = tid + it*256;
        if (i < cols) q[i] = __float2half_rn(vals[it] * inv);
    }
}

// ---------------- tiled transpose ----------------
template<typename TI, typename TO>
__global__ void transpose_t(const TI* __restrict__ in, TO* __restrict__ out,
                            int R, int Cc, int ldo, long long zi, long long zo)
{
    __shared__ float t[32][33];
    const TI* ip = in + (long long)blockIdx.z * zi;
    TO* op = out + (long long)blockIdx.z * zo;
    int c0 = blockIdx.x*32, r0 = blockIdx.y*32;
    int x = threadIdx.x, y = threadIdx.y;
    #pragma unroll
    for (int j = 0; j < 32; j += 8) {
        int r = r0 + y + j, c = c0 + x;
        if (r < R && c < Cc) t[y+j][x] = (float)ip[(long long)r*Cc + c];
    }
    __syncthreads();
    #pragma unroll
    for (int j = 0; j < 32; j += 8) {
        int c = c0 + y + j, r = r0 + x;
        if (r < R && c < Cc) op[(long long)c*ldo + r] = (TO)t[x][y+j];
    }
}

__global__ void transpose4_sq(const float* __restrict__ p0, const float* __restrict__ p1,
                              const float* __restrict__ p2, const float* __restrict__ p3,
                              __half* __restrict__ o0, __half* __restrict__ o1,
                              __half* __restrict__ o2, __half* __restrict__ o3, int D)
{
    __shared__ float t[32][33];
    int zi = blockIdx.z;
    const float* ip = (zi == 0) ? p0 : (zi == 1) ? p1 : (zi == 2) ? p2 : p3;
    __half* op = (zi == 0) ? o0 : (zi == 1) ? o1 : (zi == 2) ? o2 : o3;
    int c0 = blockIdx.x*32, r0 = blockIdx.y*32;
    int x = threadIdx.x, y = threadIdx.y;
    #pragma unroll
    for (int j = 0; j < 32; j += 8) {
        int r = r0 + y + j, c = c0 + x;
        if (r < D && c < D) t[y+j][x] = ip[(long long)r*D + c];
    }
    __syncthreads();
    #pragma unroll
    for (int j = 0; j < 32; j += 8) {
        int c = c0 + y + j, r = r0 + x;
        if (r < D && c < D) op[(long long)c*D + r] = (__half)t[x][y+j];
    }
}

__global__ void kvsT_kernel(const __half* __restrict__ that, __half* __restrict__ kvsT)
{
    __shared__ __half t[32][34];
    int g = blockIdx.z & 3, b = blockIdx.z >> 2;
    int n0 = blockIdx.y*32, e0 = blockIdx.x*32;
    const __half* in = that + (long long)b*N_*C_ + g*E_;
    __half* out = kvsT + (long long)b*E_*FN_ + g*N_;
    int x = threadIdx.x, y = threadIdx.y;
    #pragma unroll
    for (int j = 0; j < 32; j += 8) {
        int n = n0 + y + j;
        if (n < N_) t[y+j][x] = in[(long long)n*C_ + e0 + x];
    }
    __syncthreads();
    #pragma unroll
    for (int j = 0; j < 32; j += 8) {
        int n = n0 + x;
        if (n < N_) out[(long long)(e0+y+j)*FN_ + n] = t[x][y+j];
    }
}

__global__ void merge0_kernel(const __half* __restrict__ cm, __half* __restrict__ ctx0) {
    int idx = blockIdx.x * blockDim.x + threadIdx.x;
    if (idx >= BN_*E_) return;
    int b = idx / NE_;
    int rem = idx % NE_;
    int n = rem / E_;
    int e = rem % E_;
    int h = e >> 6, d = e & 63;
    ctx0[idx] = cm[((long long)(b*H_ + h)*N_ + n)*HD_ + d];
}

__global__ void copy_half8(const __half* __restrict__ src, __half* __restrict__ dst, int n8) {
    int i = blockIdx.x * blockDim.x + threadIdx.x;
    if (i < n8) ((uint4*)dst)[i] = ((const uint4*)src)[i];
}

__global__ void pack_emb(const float* __restrict__ e1, const float* __restrict__ e2,
                         const float* __restrict__ e3, const float* __restrict__ e4,
                         float* __restrict__ out) {
    const float* es[4] = {e1, e2, e3, e4};
    int g = blockIdx.y;
    int i = blockIdx.x * blockDim.x + threadIdx.x;
    if (i < BNE_) out[(long long)g*BNE_ + i] = es[g][i];
}

// ---------------- fp16 mma.sync GEMM (R7 mainloop) + optional fused stats ----------------
__device__ __forceinline__ void epi_store(
    void* __restrict__ Cv, const float* __restrict__ bias, const float* __restrict__ res,
    int ldc, int row, int gc, int M, int act, int outHalf, float alpha, float c0, float c1)
{
    if (row >= M) return;
    float2 v = make_float2(c0*alpha, c1*alpha);
    if (bias) { v.x += bias[gc]; v.y += bias[gc+1]; }
    if (act)  { v.x = gelu_f(v.x); v.y = gelu_f(v.y); }
    if (res)  { float2 rr = *(const float2*)(res + (long long)row*ldc + gc);
                v.x += rr.x; v.y += rr.y; }
    if (outHalf) {
        *(__half2*)((__half*)Cv + (long long)row*ldc + gc) = __floats2half2_rn(v.x, v.y);
    } else {
        *(float2*)((float*)Cv + (long long)row*ldc + gc) = v;
    }
}

template<int TM, int TN, int WM, int WN, int MINB>
__global__ void __launch_bounds__(256, MINB) gemm_h(
    int M, int Ncol, int K,
    const __half* __restrict__ A, int lda,
    const __half* __restrict__ B, int ldb,
    void* __restrict__ Cv, int ldc,
    const float* __restrict__ bias,
    const float* __restrict__ res,
    int act, int outHalf, float alpha,
    int D0, int D1,
    long long sA0, long long sA1, long long sA2,
    long long sB0, long long sB1, long long sB2,
    long long sC0, long long sC1, long long sC2,
    long long sBias0, long long sR0,
    float* __restrict__ sout)
{
    constexpr int WMS = TM / WM;
    constexpr int MI  = WM / 16;
    constexpr int NJ  = WN / 8;
    constexpr int ABUFW = TM * 32;
    constexpr int BBUFW = TN * 32;
    constexpr int ASLOT = (TM*2 + 255) / 256;
    constexpr int BSLOT = (TN*2 + 255) / 256;

    long long z = blockIdx.z;
    int z0 = (int)(z % D0); long long t = z / D0;
    int z1 = (int)(t % D1); int z2 = (int)(t / D1);
    A += z0*sA0 + z1*sA1 + z2*sA2;
    B += z0*sB0 + z1*sB1 + z2*sB2;
    long long coff = z0*sC0 + z1*sC1 + z2*sC2;
    Cv = outHalf ? (void*)((__half*)Cv + coff) : (void*)((float*)Cv + coff);
    if (bias) bias += z0*sBias0;
    if (res)  res  += z0*sR0;

    extern __shared__ uint32_t smw[];
    uint32_t* As = smw;
    uint32_t* Bs = smw + 2*ABUFW;

    int tid = threadIdx.x;
    int lane = tid & 31;
    int wid = tid >> 5;
    int warp_m = wid % WMS;
    int warp_n = wid / WMS;
    int row0 = blockIdx.y * TM;
    int col0 = blockIdx.x * TN;

    float acc[MI][NJ][4];
    #pragma unroll
    for (int i = 0; i < MI; i++)
        #pragma unroll
        for (int j = 0; j < NJ; j++)
            #pragma unroll
            for (int q = 0; q < 4; q++) acc[i][j][q] = 0.f;

    const __half* aPtr[ASLOT]; uint32_t aOff[ASLOT][4]; int aKh[ASLOT]; bool aV[ASLOT];
    const __half* bPtr[BSLOT]; uint32_t bOff[BSLOT][4]; int bKh[BSLOT]; bool bV[BSLOT];
    #pragma unroll
    for (int i = 0; i < ASLOT; i++) {
        int sidx = tid + i*256;
        bool inA = sidx < TM*2;
        int r = inA ? (sidx >> 1) : 0;
        int khw = (sidx & 1) * 16;
        aKh[i] = (sidx & 1) * 32;
        bool val = inA && (row0 + r) < M;
        aV[i] = val;
        aPtr[i] = A + (long long)(val ? row0 + r : 0) * lda;
        int sw = (r & 7) << 2;
        #pragma unroll
        for (int j = 0; j < 4; j++)
            aOff[i][j] = (uint32_t)((r*32 + ((khw + j*4) ^ sw)) << 2);
    }
    #pragma unroll
    for (int i = 0; i < BSLOT; i++) {
        int sidx = tid + i*256;
        bool inB = sidx < TN*2;
        int r = inB ? (sidx >> 1) : 0;
        int khw = (sidx & 1) * 16;
        bKh[i] = (sidx & 1) * 32;
        bool val = inB && (col0 + r) < Ncol;
        bV[i] = val;
        bPtr[i] = B + (long long)(val ? col0 + r : 0) * ldb;
        int sw = (r & 7) << 2;
        #pragma unroll
        for (int j = 0; j < 4; j++)
            bOff[i][j] = (uint32_t)((r*32 + ((khw + j*4) ^ sw)) << 2);
    }

    uint32_t aSm = smem_u32(As);
    uint32_t bSm = smem_u32(Bs);
    int KT = (K + 63) >> 6;
    int lr = lane >> 2;
    int lc = lane & 3;

    // prologue -> buffer 0
    #pragma unroll
    for (int i = 0; i < ASLOT; i++) {
        if ((ASLOT > 1) && (tid + i*256 >= TM*2)) continue;
        #pragma unroll
        for (int j = 0; j < 4; j++) {
            int gk = aKh[i] + j*8;
            int nb = (K - gk) * 2; nb = nb < 0 ? 0 : (nb > 16 ? 16 : nb);
            int ba = aV[i] ? nb : 0;
            cpa16(aSm + aOff[i][j], aPtr[i] + (ba ? gk : 0), ba);
        }
    }
    #pragma unroll
    for (int i = 0; i < BSLOT; i++) {
        if (tid + i*256 >= TN*2) continue;
        #pragma unroll
        for (int j = 0; j < 4; j++) {
            int gk = bKh[i] + j*8;
            int nb = (K - gk) * 2; nb = nb < 0 ? 0 : (nb > 16 ? 16 : nb);
            int bb = bV[i] ? nb : 0;
            cpa16(bSm + bOff[i][j], bPtr[i] + (bb ? gk : 0), bb);
        }
    }
    CP_COMMIT();

    for (int kt = 0; kt < KT; kt++) {
        int p = kt & 1;
        __syncthreads();
        if (kt + 1 < KT) {
            uint32_t aBo = (uint32_t)((1 - p) * ABUFW * 4);
            uint32_t bBo = (uint32_t)((1 - p) * BBUFW * 4);
            int k0 = (kt+1)*64;
            #pragma unroll
            for (int i = 0; i < ASLOT; i++) {
                if ((ASLOT > 1) && (tid + i*256 >= TM*2)) continue;
                #pragma unroll
                for (int j = 0; j < 4; j++) {
                    int gk = k0 + aKh[i] + j*8;
                    int nb = (K - gk) * 2; nb = nb < 0 ? 0 : (nb > 16 ? 16 : nb);
                    int ba = aV[i] ? nb : 0;
                    cpa16(aSm + aBo + aOff[i][j], aPtr[i] + (ba ? gk : 0), ba);
                }
            }
            #pragma unroll
            for (int i = 0; i < BSLOT; i++) {
                if (tid + i*256 >= TN*2) continue;
                #pragma unroll
                for (int j = 0; j < 4; j++) {
                    int gk = k0 + bKh[i] + j*8;
                    int nb = (K - gk) * 2; nb = nb < 0 ? 0 : (nb > 16 ? 16 : nb);
                    int bb = bV[i] ? nb : 0;
                    cpa16(bSm + bBo + bOff[i][j], bPtr[i] + (bb ? gk : 0), bb);
                }
            }
        }
        CP_COMMIT();
        CP_WAIT1();
        __syncthreads();

        const uint32_t* Ab = As + p*ABUFW;
        const uint32_t* Bb = Bs + p*BBUFW;
        #pragma unroll
        for (int ks = 0; ks < 4; ks++) {
            int w0 = ks*8 + lc;
            int w1 = w0 + 4;
            uint32_t af[MI][4], bf[NJ][2];
            #pragma unroll
            for (int i = 0; i < MI; i++) {
                int m = warp_m*WM + i*16 + lr;
                int s = (m & 7) << 2;
                af[i][0] = Ab[m*32 + (w0 ^ s)];
                af[i][1] = Ab[(m+8)*32 + (w0 ^ s)];
                af[i][2] = Ab[m*32 + (w1 ^ s)];
                af[i][3] = Ab[(m+8)*32 + (w1 ^ s)];
            }
            #pragma unroll
            for (int j = 0; j < NJ; j++) {
                int n = warp_n*WN + j*8 + lr;
                int s = (n & 7) << 2;
                bf[j][0] = Bb[n*32 + (w0 ^ s)];
                bf[j][1] = Bb[n*32 + (w1 ^ s)];
            }
            #pragma unroll
            for (int i = 0; i < MI; i++)
                #pragma unroll
                for (int j = 0; j < NJ; j++)
                    mma_f16(acc[i][j], af[i], bf[j]);
        }
    }

    #pragma unroll
    for (int i = 0; i < MI; i++) {
        int gr = row0 + warp_m*WM + i*16 + lr;
        #pragma unroll
        for (int j = 0; j < NJ; j++) {
            int gc = col0 + warp_n*WN + j*8 + lc*2;
            if (gc >= Ncol) continue;
            epi_store(Cv, bias, res, ldc, gr,   gc, M, act, outHalf, alpha, acc[i][j][0], acc[i][j][1]);
            epi_store(Cv, bias, res, ldc, gr+8, gc, M, act, outHalf, alpha, acc[i][j][2], acc[i][j][3]);
        }
    }

    if (sout) {
        float s = 0.f, q = 0.f;
        #pragma unroll
        for (int i = 0; i < MI; i++)
            #pragma unroll
            for (int j = 0; j < NJ; j++)
                #pragma unroll
                for (int qq = 0; qq < 4; qq++) {
                    float v = acc[i][j][qq];
                    s += v; q += v*v;
                }
        #pragma unroll
        for (int o = 16; o > 0; o >>= 1) {
            s += __shfl_down_sync(0xffffffffu, s, o);
            q += __shfl_down_sync(0xffffffffu, q, o);
        }
        float* shf = (float*)smw;
        __syncthreads();
        if (lane == 0) { shf[wid] = s; shf[8 + wid] = q; }
        __syncthreads();
        if (tid == 0) {
            float ts = 0.f, tq = 0.f;
            #pragma unroll
            for (int w = 0; w < 8; w++) { ts += shf[w]; tq += shf[8 + w]; }
            long long cid = (long long)blockIdx.z * (gridDim.x * gridDim.y)
                          + blockIdx.y * gridDim.x + blockIdx.x;
            sout[cid*2]   = ts;
            sout[cid*2+1] = tq;
        }
    }
}

// ---------------- host ----------------
static void* symaddr(const void* sym) {
    void* p = nullptr;
    cudaGetSymbolAddress(&p, sym);
    return p;
}

#define G1 gemm_h<128,128,64,32,2>
#define G2 gemm_h<128,256,64,64,1>
#define G3 gemm_h<128,64,32,32,2>
#define SM1 65536
#define SM2 98304
#define SM3 49152

extern "C" void kernel_launch(void* const* d_in, const int* in_sizes, int n_in,
                              void* d_out, int out_size) {
    const float* emb[4] = {(const float*)d_in[0], (const float*)d_in[1],
                           (const float*)d_in[2], (const float*)d_in[3]};
    const float* lag  = (const float*)d_in[4];
    const float* lab  = (const float*)d_in[5];
    const float* lcg  = (const float*)d_in[6];
    const float* lcb  = (const float*)d_in[7];
    const float* Wq   = (const float*)d_in[8];
    const float* Wk   = (const float*)d_in[9];
    const float* Wv   = (const float*)d_in[10];
    const float* Wo   = (const float*)d_in[11];
    const float* q_w  = (const float*)d_in[12];
    const float* k_w  = (const float*)d_in[13];
    const float* v_w  = (const float*)d_in[14];
    const float* outw = (const float*)d_in[15];
    const float* lfg  = (const float*)d_in[16];
    const float* lfb  = (const float*)d_in[17];
    const float* fc1w = (const float*)d_in[18];
    const float* fc1b = (const float*)d_in[19];
    const float* fc2w = (const float*)d_in[20];
    const float* fc2b = (const float*)d_in[21];
    float* out = (float*)d_out;

    cudaFuncSetAttribute(G1, cudaFuncAttributeMaxDynamicSharedMemorySize, SM1);
    cudaFuncSetAttribute(G2, cudaFuncAttributeMaxDynamicSharedMemorySize, SM2);
    cudaFuncSetAttribute(G3, cudaFuncAttributeMaxDynamicSharedMemorySize, SM3);

    __half* cx   = (__half*)symaddr(h_cx);   __half* cxT  = (__half*)symaddr(h_cxT);
    __half* ec   = (__half*)symaddr(h_ec);
    __half* qkv  = (__half*)symaddr(h_qkv);  __half* vcT  = (__half*)symaddr(h_vcT);
    float*  sch  = (float*)symaddr(g_sch);   __half* schh = (__half*)symaddr(h_sch);
    __half* tbuf = (__half*)symaddr(h_t);    __half* that = (__half*)symaddr(h_that);
    __half* kvsT = (__half*)symaddr(h_kvsT);
    __half* KV   = (__half*)symaddr(h_KV);   __half* VT   = (__half*)symaddr(h_VT);
    __half* Qb   = (__half*)symaddr(h_Q);
    __half* attnL= (__half*)symaddr(h_attnL);__half* attnh= (__half*)symaddr(h_attn);
    float*  parts= (float*)symaddr(g_parts); float*  rstdp= (float*)symaddr(g_rstd);
    __half* cm   = (__half*)symaddr(h_cm);   __half* ctx0 = (__half*)symaddr(h_ctx0);
    float*  embA = (float*)symaddr(g_embA);
    float*  hbuf = (float*)symaddr(g_h);     __half* xln  = (__half*)symaddr(h_xln);
    __half* x1   = (__half*)symaddr(h_x1);
    __half* qwT  = (__half*)symaddr(h_qwT);  __half* kvwT = (__half*)symaddr(h_kvwT);
    __half* Wqkv = (__half*)symaddr(h_Wqkv); __half* WoT  = (__half*)symaddr(h_WoT);
    __half* outwT= (__half*)symaddr(h_outwT);
    __half* fc1wT= (__half*)symaddr(h_fc1wT);__half* fc2wT= (__half*)symaddr(h_fc2wT);

    const long long Z = 0;
    dim3 tb(32, 8);

    // 1. fused LayerNorms + emb pack
    ln_fused_kernel<<<BN_, 256>>>(emb[0], emb[1], emb[2], emb[3], lag, lab, lcg, lcb, cx, ec);
    pack_emb<<<dim3((BNE_+255)/256, 4), 256>>>(emb[0], emb[1], emb[2], emb[3], embA);

    // 2. weight transposes — batched big squares
    transpose4_sq<<<dim3(64,64,4), tb>>>(Wq, Wk, Wv, Wo,
                                         Wqkv, Wqkv + (long long)C_*C_, Wqkv + 2LL*C_*C_, WoT, C_);
    transpose4_sq<<<dim3(25,25,2), tb>>>(k_w, v_w, k_w, k_w,
                                         kvwT, kvwT + (long long)FN_*FN_, kvwT, kvwT, FN_);
    transpose_t<float,__half><<<dim3(7,7,4),   tb>>>(q_w, qwT, N_, N_, LP_, (long long)N_*N_, (long long)N_*LP_);
    transpose_t<float,__half><<<dim3(16,16,4), tb>>>(outw, outwT, E_, E_, E_, (long long)E_*E_, (long long)E_*E_);
    transpose_t<float,__half><<<dim3(64,16,4), tb>>>(fc1w, fc1wT, E_, 2048, E_, (long long)E_*2048, (long long)2048*E_);
    transpose_t<float,__half><<<dim3(16,64,4), tb>>>(fc2w, fc2wT, 2048, E_, 2048, (long long)2048*E_, (long long)E_*2048);
    transpose_t<__half,__half><<<dim3(16,7,64), tb>>>(cx, cxT, N_, E_, LP_, (long long)NE_, (long long)E_*LP_);

    // 3. channel projections merged QKV (G2, 600 CTAs)
    {
        dim3 g(8, 25, 3);
        G2<<<g,256,SM2>>>(BN_, C_, C_, ec, C_, Wqkv, C_, qkv, C_, nullptr, nullptr, 0, 1, 1.f,
                          3, 1,
                          Z, Z, Z,
                          (long long)C_*C_, Z, Z,
                          (long long)BN_*C_, Z, Z,
                          Z, Z, nullptr);
    }
    transpose_t<__half,__half><<<dim3(64,7,16), tb>>>(qkv + 2LL*BN_*C_, vcT, N_, C_, LP_,
                                                      (long long)N_*C_, (long long)C_*LP_);

    // 4. channel scores per (h,b): fp32 logits
    {
        dim3 g(2, 2, B_*H_);
        G1<<<g,256,SM1>>>(N_, N_, HDC_, qkv, C_, qkv + (long long)BN_*C_, C_, sch, N_,
                          nullptr, nullptr, 0, 0, 0.0625f,
                          H_, B_,
                          256LL, (long long)N_*C_, Z,
                          256LL, (long long)N_*C_, Z,
                          (long long)SCHZ_, (long long)H_*SCHZ_, Z,
                          Z, Z, nullptr);
    }
    // 5. channel softmax -> half probs
    softmax_fix<1,false,float><<<B_*H_*N_, 256>>>(sch, schh, N_, LP_, 1, nullptr, 1.f);

    // 6. T = s @ v per (h,b)
    {
        dim3 g(1, 2, B_*H_);
        G2<<<g,256,SM2>>>(N_, HDC_, N_, schh, LP_, vcT, LP_, tbuf, C_, nullptr, nullptr, 0, 1, 1.f,
                          H_, B_,
                          (long long)N_*LP_, (long long)H_*N_*LP_, Z,
                          (long long)256*LP_, (long long)C_*LP_, Z,
                          256LL, (long long)N_*C_, Z,
                          Z, Z, nullptr);
    }
    // 7. T_hat = T @ Wo (G2, 200 CTAs)
    {
        dim3 g(8, 25, 1);
        G2<<<g,256,SM2>>>(BN_, C_, C_, tbuf, C_, WoT, C_, that, C_, nullptr, nullptr, 0, 1, 1.f,
                          1,1, Z,Z,Z, Z,Z,Z, Z,Z,Z, Z,Z, nullptr);
    }
    // 8. fused KV_S reshape + transpose
    kvsT_kernel<<<dim3(16, 7, 64), tb>>>(that, kvsT);

    // 9. K/V token-mix merged (G2)
    {
        dim3 g(2, 7, 2*B_);
        G2<<<g,256,SM2>>>(FN_, E_, FN_, kvwT, FN_, kvsT, FN_, KV, E_, nullptr, nullptr, 0, 1, 1.f,
                          2, B_,
                          (long long)FN_*FN_, Z, Z,
                          Z, (long long)E_*FN_, Z,
                          (long long)B_*FNE_, (long long)FNE_, Z,
                          Z, Z, nullptr);
    }
    transpose_t<__half,__half><<<dim3(16,25,16), tb>>>(KV + (long long)B_*FNE_, VT, FN_, E_, FN_,
                                                       (long long)FNE_, (long long)E_*FN_);

    // 10. Q token-mix per (b,g)
    {
        dim3 g(2, 2, 4*B_);
        G2<<<g,256,SM2>>>(N_, E_, N_, qwT, LP_, cxT, LP_, Qb, E_, nullptr, nullptr, 0, 1, 1.f,
                          B_, 4,
                          Z, (long long)N_*LP_, Z,
                          (long long)E_*LP_, (long long)B_*E_*LP_, Z,
                          (long long)NE_, (long long)BNE_, Z,
                          Z, Z, nullptr);
    }
    // 11. spatial logits per (h,b,g): HALF logits + fused fp32 stats partials (G1, 2 CTA/SM)
    {
        dim3 g(7, 2, 512);
        G1<<<g,256,SM1>>>(N_, FN_, HD_, Qb, E_, KV, E_, attnL, FN_, nullptr, nullptr, 0, 1, 1.f,
                          H_, B_,
                          64LL, (long long)NE_,  (long long)BNE_,
                          64LL, (long long)FNE_, Z,
                          (long long)ATTZ_, (long long)H_*ATTZ_, (long long)B_*H_*ATTZ_,
                          Z, Z, parts);
    }
    // 12-13. rstd + normalized softmax (half logits in, half probs out)
    rstd_parts<<<512, 32>>>(parts, rstdp, 14);
    softmax_fix<4,true,__half><<<512*N_, 256>>>(attnL, attnh, FN_, FN_, N_, rstdp, 1.f);

    // 14. ctx = p @ Vh per (h,b,g) -> cm (G3, 2 CTA/SM)
    {
        dim3 g(1, 2, 512);
        G3<<<g,256,SM3>>>(N_, HD_, FN_, attnh, FN_, VT, FN_, cm, HD_, nullptr, nullptr, 0, 1, 1.f,
                          H_, B_,
                          (long long)ATTZ_, (long long)H_*ATTZ_, (long long)B_*H_*ATTZ_,
                          (long long)HD_*FN_, (long long)E_*FN_, Z,
                          (long long)N_*HD_, (long long)H_*N_*HD_, (long long)BNE_,
                          Z, Z, nullptr);
    }
    // 15. branch-0 head permute -> slot 0
    merge0_kernel<<<(BN_*E_ + 255)/256, 256>>>(cm, ctx0);
    copy_half8<<<(BNE_/8 + 255)/256, 256>>>(ctx0, cm, BNE_/8);

    // 16. out projection + residual-1 merged over g (G2)
    {
        dim3 g(2, 25, 4);
        G2<<<g,256,SM2>>>(BN_, E_, E_, cm, E_, outwT, E_, hbuf, E_,
                          nullptr, embA, 0, 0, 1.f,
                          4, 1,
                          (long long)BNE_, Z, Z,
                          (long long)E_*E_, Z, Z,
                          (long long)BNE_, Z, Z,
                          Z, (long long)BNE_, nullptr);
    }
    // 17. FFN LayerNorm
    ln_rows_kernel<<<4*BN_, 256>>>(hbuf, lfg, lfb, xln, BN_);

    // 18. fc1 + bias + GELU per g (G2, 800 CTAs)
    {
        dim3 g(8, 25, 4);
        G2<<<g,256,SM2>>>(BN_, 4*E_, E_, xln, E_, fc1wT, E_, x1, 4*E_,
                          fc1b, nullptr, 1, 1, 1.f,
                          4, 1,
                          (long long)BNE_, Z, Z,
                          (long long)2048*E_, Z, Z,
                          (long long)BN_*2048, Z, Z,
                          (long long)2048, Z, nullptr);
    }
    // 19. fc2 + bias + residual-2 -> out (G2)
    {
        dim3 g(2, 25, 4);
        G2<<<g,256,SM2>>>(BN_, E_, 4*E_, x1, 4*E_, fc2wT, 4*E_, out, E_,
                          fc2b, hbuf, 0, 0, 1.f,
                          4, 1,
                          (long long)BN_*2048, Z, Z,
                          (long long)E_*2048, Z, Z,
                          (long long)BNE_, Z, Z,
                          (long long)E_, (long long)BNE_, nullptr);
    }
}

// round 14
// speedup vs baseline: 1.1528x; 1.0793x over previous
#include <cuda_runtime.h>
#include <cuda_fp16.h>
#include <cstdint>
#include <math.h>

#define B_     16
#define N_     196
#define E_     512
#define H_     8
#define HD_    64
#define C_     2048
#define HDC_   256
#define FN_    784
#define BN_    3136
#define NE_    100352
#define FNE_   401408
#define BNE_   1605632
#define SCHZ_  38416
#define ATTZ_  153664
#define LP_    200

// ---------------- scratch ----------------
__device__ __align__(128) __half h_cx  [4*BN_*E_];
__device__ __align__(128) __half h_cxT [4*B_*E_*LP_];
__device__ __align__(128) __half h_ec  [BN_*C_];
__device__ __align__(128) __half h_qkv [3LL*BN_*C_];
__device__ __align__(128) __half h_vcT [B_*C_*LP_];
__device__ __align__(128) float  g_sch [B_*H_*N_*N_];
__device__ __align__(128) __half h_sch [B_*H_*N_*LP_];
__device__ __align__(128) __half h_t   [BN_*C_];
__device__ __align__(128) __half h_that[BN_*C_];
__device__ __align__(128) __half h_kvsT[B_*E_*FN_];
__device__ __align__(128) __half h_KV  [2*B_*FN_*E_];
__device__ __align__(128) __half h_VT  [B_*E_*FN_];
__device__ __align__(128) __half h_Q   [4*BN_*E_];
__device__ __align__(128) __half h_attnL[512u*196*784];   // half logits
__device__ __align__(128) __half h_attn [512u*196*784];   // half probs
__device__ __align__(128) float  g_parts[512*14*2];
__device__ __align__(128) float  g_rstd[512];
__device__ __align__(128) __half h_cm  [4LL*BNE_];
__device__ __align__(128) __half h_ctx0[BNE_];
__device__ __align__(128) float  g_embA[4LL*BNE_];
__device__ __align__(128) float  g_h   [4*BN_*E_];
__device__ __align__(128) __half h_xln [4*BN_*E_];
__device__ __align__(128) __half h_x1  [4*BN_*2048];
__device__ __align__(128) __half h_qwT [4*N_*LP_];
__device__ __align__(128) __half h_kvwT[2*FN_*FN_];
__device__ __align__(128) __half h_Wqkv[3LL*C_*C_];
__device__ __align__(128) __half h_WoT [C_*C_];
__device__ __align__(128) __half h_outwT[4*E_*E_];
__device__ __align__(128) __half h_fc1wT[4*2048*E_];
__device__ __align__(128) __half h_fc2wT[4*E_*2048];

// ---------------- helpers ----------------
__device__ __forceinline__ uint32_t smem_u32(const void* p) {
    uint32_t a;
    asm("{ .reg .u64 t; cvta.to.shared.u64 t, %1; cvt.u32.u64 %0, t; }" : "=r"(a) : "l"(p));
    return a;
}
__device__ __forceinline__ void mma_f16(float* d, const uint32_t* a, const uint32_t* b) {
    asm volatile(
        "mma.sync.aligned.m16n8k16.row.col.f32.f16.f16.f32 "
        "{%0,%1,%2,%3}, {%4,%5,%6,%7}, {%8,%9}, {%0,%1,%2,%3};"
        : "+f"(d[0]), "+f"(d[1]), "+f"(d[2]), "+f"(d[3])
        : "r"(a[0]), "r"(a[1]), "r"(a[2]), "r"(a[3]), "r"(b[0]), "r"(b[1]));
}
__device__ __forceinline__ float gelu_f(float v) {
    return 0.5f * v * (1.f + erff(v * 0.70710678118654752f));
}
__device__ __forceinline__ void cpa16(uint32_t dst, const __half* src, int bytes) {
    asm volatile("cp.async.ca.shared.global [%0], [%1], 16, %2;"
                 :: "r"(dst), "l"(src), "r"(bytes) : "memory");
}
#define CP_COMMIT() asm volatile("cp.async.commit_group;" ::: "memory")
#define CP_WAIT1()  asm volatile("cp.async.wait_group 1;" ::: "memory")

// ---------------- reductions ----------------
__device__ __forceinline__ float block_sum(float v, float* sh) {
    int tid = threadIdx.x;
    #pragma unroll
    for (int o = 16; o > 0; o >>= 1) v += __shfl_down_sync(0xffffffffu, v, o);
    if ((tid & 31) == 0) sh[tid >> 5] = v;
    __syncthreads();
    if (tid < 32) {
        float t = (tid < (int)(blockDim.x >> 5)) ? sh[tid] : 0.f;
        #pragma unroll
        for (int o = 16; o > 0; o >>= 1) t += __shfl_down_sync(0xffffffffu, t, o);
        if (tid == 0) sh[0] = t;
    }
    __syncthreads();
    float r = sh[0];
    __syncthreads();
    return r;
}
__device__ __forceinline__ float block_max(float v, float* sh) {
    int tid = threadIdx.x;
    #pragma unroll
    for (int o = 16; o > 0; o >>= 1) v = fmaxf(v, __shfl_down_sync(0xffffffffu, v, o));
    if ((tid & 31) == 0) sh[tid >> 5] = v;
    __syncthreads();
    if (tid < 32) {
        float t = (tid < (int)(blockDim.x >> 5)) ? sh[tid] : -INFINITY;
        #pragma unroll
        for (int o = 16; o > 0; o >>= 1) t = fmaxf(t, __shfl_down_sync(0xffffffffu, t, o));
        if (tid == 0) sh[0] = t;
    }
    __syncthreads();
    float r = sh[0];
    __syncthreads();
    return r;
}

// ---------------- LN ----------------
__global__ void __launch_bounds__(256) ln_fused_kernel(
    const float* __restrict__ e1, const float* __restrict__ e2,
    const float* __restrict__ e3, const float* __restrict__ e4,
    const float* __restrict__ lag, const float* __restrict__ lab,
    const float* __restrict__ lcg, const float* __restrict__ lcb,
    __half* __restrict__ cx, __half* __restrict__ ec)
{
    __shared__ float sh[32];
    int token = blockIdx.x;
    int tid = threadIdx.x;
    const float* es[4] = {e1, e2, e3, e4};
    float x[4][2], mg[4], rg[4];
    float stot = 0.f, sstot = 0.f;
    #pragma unroll
    for (int g = 0; g < 4; g++) {
        const float* p = es[g] + (long long)token * E_;
        x[g][0] = p[tid]; x[g][1] = p[tid + 256];
        float s  = block_sum(x[g][0] + x[g][1], sh);
        float ss = block_sum(x[g][0]*x[g][0] + x[g][1]*x[g][1], sh);
        float m = s * (1.f/512.f);
        float v = ss * (1.f/512.f) - m*m;
        mg[g] = m; rg[g] = rsqrtf(v + 1e-6f);
        stot += s; sstot += ss;
    }
    float m = stot * (1.f/2048.f);
    float r = rsqrtf(sstot * (1.f/2048.f) - m*m + 1e-6f);
    #pragma unroll
    for (int g = 0; g < 4; g++) {
        #pragma unroll
        for (int j = 0; j < 2; j++) {
            int e = tid + j*256;
            float xv = x[g][j];
            cx[((long long)g*BN_ + token)*E_ + e] =
                __float2half_rn((xv - mg[g]) * rg[g] * lag[g*E_+e] + lab[g*E_+e]);
            ec[(long long)token*C_ + g*E_ + e] =
                __float2half_rn((xv - m) * r * lcg[g*E_+e] + lcb[g*E_+e]);
        }
    }
}

__global__ void __launch_bounds__(256) ln_rows_kernel(
    const float* __restrict__ X, const float* __restrict__ gamma,
    const float* __restrict__ beta, __half* __restrict__ Y, int rowsPerG)
{
    __shared__ float sh[32];
    long long row = blockIdx.x;
    int tid = threadIdx.x;
    int g = (int)(row / rowsPerG);
    const float* p = X + row * E_;
    float x0 = p[tid], x1 = p[tid+256];
    float s  = block_sum(x0 + x1, sh);
    float ss = block_sum(x0*x0 + x1*x1, sh);
    float m = s * (1.f/512.f);
    float r = rsqrtf(ss * (1.f/512.f) - m*m + 1e-6f);
    __half* q = Y + row * E_;
    q[tid]     = __float2half_rn((x0 - m) * r * gamma[g*E_+tid]     + beta[g*E_+tid]);
    q[tid+256] = __float2half_rn((x1 - m) * r * gamma[g*E_+tid+256] + beta[g*E_+tid+256]);
}

// ---------------- rstd from per-CTA partials ----------------
__global__ void rstd_parts(const float* __restrict__ parts, float* __restrict__ rstd, int nparts) {
    int z = blockIdx.x;
    int t = threadIdx.x;
    float s = 0.f, q = 0.f;
    if (t < nparts) { s = parts[(z*nparts+t)*2]; q = parts[(z*nparts+t)*2+1]; }
    #pragma unroll
    for (int o = 16; o > 0; o >>= 1) {
        s += __shfl_down_sync(0xffffffffu, s, o);
        q += __shfl_down_sync(0xffffffffu, q, o);
    }
    if (t == 0) {
        float m = s * (1.f/(float)ATTZ_);
        rstd[z] = rsqrtf(q * (1.f/(float)ATTZ_) - m*m + 1e-5f);
    }
}

// ---------------- softmax: TI logits -> half probs ----------------
template<int NIT, bool PERZ, typename TI>
__global__ void __launch_bounds__(256) softmax_fix(
    const TI* __restrict__ S, __half* __restrict__ O,
    int cols, int ldo, int rowsPerZ,
    const float* __restrict__ rstd, float scale)
{
    __shared__ float sh[32];
    long long row = blockIdx.x;
    const TI* p = S + row * cols;
    __half* q = O + row * ldo;
    float sc = PERZ ? rstd[(int)(row / rowsPerZ)] : scale;
    int tid = threadIdx.x;
    float vals[NIT];
    float mx = -INFINITY;
    #pragma unroll
    for (int it = 0; it < NIT; it++) {
        int i = tid + it*256;
        float t = (i < cols) ? (float)p[i]*sc : -INFINITY;
        vals[it] = t;
        mx = fmaxf(mx, t);
    }
    mx = block_max(mx, sh);
    float s = 0.f;
    #pragma unroll
    for (int it = 0; it < NIT; it++) {
        float e = expf(vals[it] - mx);
        vals[it] = e;
        s += e;
    }
    s = block_sum(s, sh);
    float inv = 1.f / s;
    #pragma unroll
    for (int it = 0; it < NIT; it++) {
        int i = tid + it*256;
        if (i < cols) q[i] = __float2half_rn(vals[it] * inv);
    }
}

// ---------------- tiled transpose ----------------
template<typename TI, typename TO>
__global__ void transpose_t(const TI* __restrict__ in, TO* __restrict__ out,
                            int R, int Cc, int ldo, long long zi, long long zo)
{
    __shared__ float t[32][33];
    const TI* ip = in + (long long)blockIdx.z * zi;
    TO* op = out + (long long)blockIdx.z * zo;
    int c0 = blockIdx.x*32, r0 = blockIdx.y*32;
    int x = threadIdx.x, y = threadIdx.y;
    #pragma unroll
    for (int j = 0; j < 32; j += 8) {
        int r = r0 + y + j, c = c0 + x;
        if (r < R && c < Cc) t[y+j][x] = (float)ip[(long long)r*Cc + c];
    }
    __syncthreads();
    #pragma unroll
    for (int j = 0; j < 32; j += 8) {
        int c = c0 + y + j, r = r0 + x;
        if (r < R && c < Cc) op[(long long)c*ldo + r] = (TO)t[x][y+j];
    }
}

__global__ void transpose4_sq(const float* __restrict__ p0, const float* __restrict__ p1,
                              const float* __restrict__ p2, const float* __restrict__ p3,
                              __half* __restrict__ o0, __half* __restrict__ o1,
                              __half* __restrict__ o2, __half* __restrict__ o3, int D)
{
    __shared__ float t[32][33];
    int zi = blockIdx.z;
    const float* ip = (zi == 0) ? p0 : (zi == 1) ? p1 : (zi == 2) ? p2 : p3;
    __half* op = (zi == 0) ? o0 : (zi == 1) ? o1 : (zi == 2) ? o2 : o3;
    int c0 = blockIdx.x*32, r0 = blockIdx.y*32;
    int x = threadIdx.x, y = threadIdx.y;
    #pragma unroll
    for (int j = 0; j < 32; j += 8) {
        int r = r0 + y + j, c = c0 + x;
        if (r < D && c < D) t[y+j][x] = ip[(long long)r*D + c];
    }
    __syncthreads();
    #pragma unroll
    for (int j = 0; j < 32; j += 8) {
        int c = c0 + y + j, r = r0 + x;
        if (r < D && c < D) op[(long long)c*D + r] = (__half)t[x][y+j];
    }
}

__global__ void kvsT_kernel(const __half* __restrict__ that, __half* __restrict__ kvsT)
{
    __shared__ __half t[32][34];
    int g = blockIdx.z & 3, b = blockIdx.z >> 2;
    int n0 = blockIdx.y*32, e0 = blockIdx.x*32;
    const __half* in = that + (long long)b*N_*C_ + g*E_;
    __half* out = kvsT + (long long)b*E_*FN_ + g*N_;
    int x = threadIdx.x, y = threadIdx.y;
    #pragma unroll
    for (int j = 0; j < 32; j += 8) {
        int n = n0 + y + j;
        if (n < N_) t[y+j][x] = in[(long long)n*C_ + e0 + x];
    }
    __syncthreads();
    #pragma unroll
    for (int j = 0; j < 32; j += 8) {
        int n = n0 + x;
        if (n < N_) out[(long long)(e0+y+j)*FN_ + n] = t[x][y+j];
    }
}

__global__ void merge0_kernel(const __half* __restrict__ cm, __half* __restrict__ ctx0) {
    int idx = blockIdx.x * blockDim.x + threadIdx.x;
    if (idx >= BN_*E_) return;
    int b = idx / NE_;
    int rem = idx % NE_;
    int n = rem / E_;
    int e = rem % E_;
    int h = e >> 6, d = e & 63;
    ctx0[idx] = cm[((long long)(b*H_ + h)*N_ + n)*HD_ + d];
}

__global__ void copy_half8(const __half* __restrict__ src, __half* __restrict__ dst, int n8) {
    int i = blockIdx.x * blockDim.x + threadIdx.x;
    if (i < n8) ((uint4*)dst)[i] = ((const uint4*)src)[i];
}

__global__ void pack_emb(const float* __restrict__ e1, const float* __restrict__ e2,
                         const float* __restrict__ e3, const float* __restrict__ e4,
                         float* __restrict__ out) {
    const float* es[4] = {e1, e2, e3, e4};
    int g = blockIdx.y;
    int i = blockIdx.x * blockDim.x + threadIdx.x;
    if (i < BNE_) out[(long long)g*BNE_ + i] = es[g][i];
}

// ---------------- fp16 mma.sync GEMM (R7 mainloop) + optional fused stats ----------------
__device__ __forceinline__ void epi_store(
    void* __restrict__ Cv, const float* __restrict__ bias, const float* __restrict__ res,
    int ldc, int row, int gc, int M, int act, int outHalf, float alpha, float c0, float c1)
{
    if (row >= M) return;
    float2 v = make_float2(c0*alpha, c1*alpha);
    if (bias) { v.x += bias[gc]; v.y += bias[gc+1]; }
    if (act)  { v.x = gelu_f(v.x); v.y = gelu_f(v.y); }
    if (res)  { float2 rr = *(const float2*)(res + (long long)row*ldc + gc);
                v.x += rr.x; v.y += rr.y; }
    if (outHalf) {
        *(__half2*)((__half*)Cv + (long long)row*ldc + gc) = __floats2half2_rn(v.x, v.y);
    } else {
        *(float2*)((float*)Cv + (long long)row*ldc + gc) = v;
    }
}

template<int TM, int TN, int WM, int WN, int MINB>
__global__ void __launch_bounds__(256, MINB) gemm_h(
    int M, int Ncol, int K,
    const __half* __restrict__ A, int lda,
    const __half* __restrict__ B, int ldb,
    void* __restrict__ Cv, int ldc,
    const float* __restrict__ bias,
    const float* __restrict__ res,
    int act, int outHalf, float alpha,
    int D0, int D1,
    long long sA0, long long sA1, long long sA2,
    long long sB0, long long sB1, long long sB2,
    long long sC0, long long sC1, long long sC2,
    long long sBias0, long long sR0,
    float* __restrict__ sout)
{
    constexpr int WMS = TM / WM;
    constexpr int MI  = WM / 16;
    constexpr int NJ  = WN / 8;
    constexpr int ABUFW = TM * 32;
    constexpr int BBUFW = TN * 32;
    constexpr int ASLOT = (TM*2 + 255) / 256;
    constexpr int BSLOT = (TN*2 + 255) / 256;

    long long z = blockIdx.z;
    int z0 = (int)(z % D0); long long t = z / D0;
    int z1 = (int)(t % D1); int z2 = (int)(t / D1);
    A += z0*sA0 + z1*sA1 + z2*sA2;
    B += z0*sB0 + z1*sB1 + z2*sB2;
    long long coff = z0*sC0 + z1*sC1 + z2*sC2;
    Cv = outHalf ? (void*)((__half*)Cv + coff) : (void*)((float*)Cv + coff);
    if (bias) bias += z0*sBias0;
    if (res)  res  += z0*sR0;

    extern __shared__ uint32_t smw[];
    uint32_t* As = smw;
    uint32_t* Bs = smw + 2*ABUFW;

    int tid = threadIdx.x;
    int lane = tid & 31;
    int wid = tid >> 5;
    int warp_m = wid % WMS;
    int warp_n = wid / WMS;
    int row0 = blockIdx.y * TM;
    int col0 = blockIdx.x * TN;

    float acc[MI][NJ][4];
    #pragma unroll
    for (int i = 0; i < MI; i++)
        #pragma unroll
        for (int j = 0; j < NJ; j++)
            #pragma unroll
            for (int q = 0; q < 4; q++) acc[i][j][q] = 0.f;

    const __half* aPtr[ASLOT]; uint32_t aOff[ASLOT][4]; int aKh[ASLOT]; bool aV[ASLOT];
    const __half* bPtr[BSLOT]; uint32_t bOff[BSLOT][4]; int bKh[BSLOT]; bool bV[BSLOT];
    #pragma unroll
    for (int i = 0; i < ASLOT; i++) {
        int sidx = tid + i*256;
        bool inA = sidx < TM*2;
        int r = inA ? (sidx >> 1) : 0;
        int khw = (sidx & 1) * 16;
        aKh[i] = (sidx & 1) * 32;
        bool val = inA && (row0 + r) < M;
        aV[i] = val;
        aPtr[i] = A + (long long)(val ? row0 + r : 0) * lda;
        int sw = (r & 7) << 2;
        #pragma unroll
        for (int j = 0; j < 4; j++)
            aOff[i][j] = (uint32_t)((r*32 + ((khw + j*4) ^ sw)) << 2);
    }
    #pragma unroll
    for (int i = 0; i < BSLOT; i++) {
        int sidx = tid + i*256;
        bool inB = sidx < TN*2;
        int r = inB ? (sidx >> 1) : 0;
        int khw = (sidx & 1) * 16;
        bKh[i] = (sidx & 1) * 32;
        bool val = inB && (col0 + r) < Ncol;
        bV[i] = val;
        bPtr[i] = B + (long long)(val ? col0 + r : 0) * ldb;
        int sw = (r & 7) << 2;
        #pragma unroll
        for (int j = 0; j < 4; j++)
            bOff[i][j] = (uint32_t)((r*32 + ((khw + j*4) ^ sw)) << 2);
    }

    uint32_t aSm = smem_u32(As);
    uint32_t bSm = smem_u32(Bs);
    int KT = (K + 63) >> 6;
    int lr = lane >> 2;
    int lc = lane & 3;

    // prologue -> buffer 0
    #pragma unroll
    for (int i = 0; i < ASLOT; i++) {
        if ((ASLOT > 1) && (tid + i*256 >= TM*2)) continue;
        #pragma unroll
        for (int j = 0; j < 4; j++) {
            int gk = aKh[i] + j*8;
            int nb = (K - gk) * 2; nb = nb < 0 ? 0 : (nb > 16 ? 16 : nb);
            int ba = aV[i] ? nb : 0;
            cpa16(aSm + aOff[i][j], aPtr[i] + (ba ? gk : 0), ba);
        }
    }
    #pragma unroll
    for (int i = 0; i < BSLOT; i++) {
        if (tid + i*256 >= TN*2) continue;
        #pragma unroll
        for (int j = 0; j < 4; j++) {
            int gk = bKh[i] + j*8;
            int nb = (K - gk) * 2; nb = nb < 0 ? 0 : (nb > 16 ? 16 : nb);
            int bb = bV[i] ? nb : 0;
            cpa16(bSm + bOff[i][j], bPtr[i] + (bb ? gk : 0), bb);
        }
    }
    CP_COMMIT();

    for (int kt = 0; kt < KT; kt++) {
        int p = kt & 1;
        __syncthreads();
        if (kt + 1 < KT) {
            uint32_t aBo = (uint32_t)((1 - p) * ABUFW * 4);
            uint32_t bBo = (uint32_t)((1 - p) * BBUFW * 4);
            int k0 = (kt+1)*64;
            #pragma unroll
            for (int i = 0; i < ASLOT; i++) {
                if ((ASLOT > 1) && (tid + i*256 >= TM*2)) continue;
                #pragma unroll
                for (int j = 0; j < 4; j++) {
                    int gk = k0 + aKh[i] + j*8;
                    int nb = (K - gk) * 2; nb = nb < 0 ? 0 : (nb > 16 ? 16 : nb);
                    int ba = aV[i] ? nb : 0;
                    cpa16(aSm + aBo + aOff[i][j], aPtr[i] + (ba ? gk : 0), ba);
                }
            }
            #pragma unroll
            for (int i = 0; i < BSLOT; i++) {
                if (tid + i*256 >= TN*2) continue;
                #pragma unroll
                for (int j = 0; j < 4; j++) {
                    int gk = k0 + bKh[i] + j*8;
                    int nb = (K - gk) * 2; nb = nb < 0 ? 0 : (nb > 16 ? 16 : nb);
                    int bb = bV[i] ? nb : 0;
                    cpa16(bSm + bBo + bOff[i][j], bPtr[i] + (bb ? gk : 0), bb);
                }
            }
        }
        CP_COMMIT();
        CP_WAIT1();
        __syncthreads();

        const uint32_t* Ab = As + p*ABUFW;
        const uint32_t* Bb = Bs + p*BBUFW;
        #pragma unroll
        for (int ks = 0; ks < 4; ks++) {
            int w0 = ks*8 + lc;
            int w1 = w0 + 4;
            uint32_t af[MI][4], bf[NJ][2];
            #pragma unroll
            for (int i = 0; i < MI; i++) {
                int m = warp_m*WM + i*16 + lr;
                int s = (m & 7) << 2;
                af[i][0] = Ab[m*32 + (w0 ^ s)];
                af[i][1] = Ab[(m+8)*32 + (w0 ^ s)];
                af[i][2] = Ab[m*32 + (w1 ^ s)];
                af[i][3] = Ab[(m+8)*32 + (w1 ^ s)];
            }
            #pragma unroll
            for (int j = 0; j < NJ; j++) {
                int n = warp_n*WN + j*8 + lr;
                int s = (n & 7) << 2;
                bf[j][0] = Bb[n*32 + (w0 ^ s)];
                bf[j][1] = Bb[n*32 + (w1 ^ s)];
            }
            #pragma unroll
            for (int i = 0; i < MI; i++)
                #pragma unroll
                for (int j = 0; j < NJ; j++)
                    mma_f16(acc[i][j], af[i], bf[j]);
        }
    }

    #pragma unroll
    for (int i = 0; i < MI; i++) {
        int gr = row0 + warp_m*WM + i*16 + lr;
        #pragma unroll
        for (int j = 0; j < NJ; j++) {
            int gc = col0 + warp_n*WN + j*8 + lc*2;
            if (gc >= Ncol) continue;
            epi_store(Cv, bias, res, ldc, gr,   gc, M, act, outHalf, alpha, acc[i][j][0], acc[i][j][1]);
            epi_store(Cv, bias, res, ldc, gr+8, gc, M, act, outHalf, alpha, acc[i][j][2], acc[i][j][3]);
        }
    }

    if (sout) {
        float s = 0.f, q = 0.f;
        #pragma unroll
        for (int i = 0; i < MI; i++)
            #pragma unroll
            for (int j = 0; j < NJ; j++)
                #pragma unroll
                for (int qq = 0; qq < 4; qq++) {
                    float v = acc[i][j][qq];
                    s += v; q += v*v;
                }
        #pragma unroll
        for (int o = 16; o > 0; o >>= 1) {
            s += __shfl_down_sync(0xffffffffu, s, o);
            q += __shfl_down_sync(0xffffffffu, q, o);
        }
        float* shf = (float*)smw;
        __syncthreads();
        if (lane == 0) { shf[wid] = s; shf[8 + wid] = q; }
        __syncthreads();
        if (tid == 0) {
            float ts = 0.f, tq = 0.f;
            #pragma unroll
            for (int w = 0; w < 8; w++) { ts += shf[w]; tq += shf[8 + w]; }
            long long cid = (long long)blockIdx.z * (gridDim.x * gridDim.y)
                          + blockIdx.y * gridDim.x + blockIdx.x;
            sout[cid*2]   = ts;
            sout[cid*2+1] = tq;
        }
    }
}

// ---------------- host ----------------
static void* symaddr(const void* sym) {
    void* p = nullptr;
    cudaGetSymbolAddress(&p, sym);
    return p;
}

#define G1 gemm_h<128,128,64,32,2>
#define G2 gemm_h<128,256,64,64,1>
#define G3 gemm_h<128,64,32,32,2>
#define SM1 65536
#define SM2 98304
#define SM3 49152

extern "C" void kernel_launch(void* const* d_in, const int* in_sizes, int n_in,
                              void* d_out, int out_size) {
    const float* emb[4] = {(const float*)d_in[0], (const float*)d_in[1],
                           (const float*)d_in[2], (const float*)d_in[3]};
    const float* lag  = (const float*)d_in[4];
    const float* lab  = (const float*)d_in[5];
    const float* lcg  = (const float*)d_in[6];
    const float* lcb  = (const float*)d_in[7];
    const float* Wq   = (const float*)d_in[8];
    const float* Wk   = (const float*)d_in[9];
    const float* Wv   = (const float*)d_in[10];
    const float* Wo   = (const float*)d_in[11];
    const float* q_w  = (const float*)d_in[12];
    const float* k_w  = (const float*)d_in[13];
    const float* v_w  = (const float*)d_in[14];
    const float* outw = (const float*)d_in[15];
    const float* lfg  = (const float*)d_in[16];
    const float* lfb  = (const float*)d_in[17];
    const float* fc1w = (const float*)d_in[18];
    const float* fc1b = (const float*)d_in[19];
    const float* fc2w = (const float*)d_in[20];
    const float* fc2b = (const float*)d_in[21];
    float* out = (float*)d_out;

    cudaFuncSetAttribute(G1, cudaFuncAttributeMaxDynamicSharedMemorySize, SM1);
    cudaFuncSetAttribute(G2, cudaFuncAttributeMaxDynamicSharedMemorySize, SM2);
    cudaFuncSetAttribute(G3, cudaFuncAttributeMaxDynamicSharedMemorySize, SM3);

    __half* cx   = (__half*)symaddr(h_cx);   __half* cxT  = (__half*)symaddr(h_cxT);
    __half* ec   = (__half*)symaddr(h_ec);
    __half* qkv  = (__half*)symaddr(h_qkv);  __half* vcT  = (__half*)symaddr(h_vcT);
    float*  sch  = (float*)symaddr(g_sch);   __half* schh = (__half*)symaddr(h_sch);
    __half* tbuf = (__half*)symaddr(h_t);    __half* that = (__half*)symaddr(h_that);
    __half* kvsT = (__half*)symaddr(h_kvsT);
    __half* KV   = (__half*)symaddr(h_KV);   __half* VT   = (__half*)symaddr(h_VT);
    __half* Qb   = (__half*)symaddr(h_Q);
    __half* attnL= (__half*)symaddr(h_attnL);__half* attnh= (__half*)symaddr(h_attn);
    float*  parts= (float*)symaddr(g_parts); float*  rstdp= (float*)symaddr(g_rstd);
    __half* cm   = (__half*)symaddr(h_cm);   __half* ctx0 = (__half*)symaddr(h_ctx0);
    float*  embA = (float*)symaddr(g_embA);
    float*  hbuf = (float*)symaddr(g_h);     __half* xln  = (__half*)symaddr(h_xln);
    __half* x1   = (__half*)symaddr(h_x1);
    __half* qwT  = (__half*)symaddr(h_qwT);  __half* kvwT = (__half*)symaddr(h_kvwT);
    __half* Wqkv = (__half*)symaddr(h_Wqkv); __half* WoT  = (__half*)symaddr(h_WoT);
    __half* outwT= (__half*)symaddr(h_outwT);
    __half* fc1wT= (__half*)symaddr(h_fc1wT);__half* fc2wT= (__half*)symaddr(h_fc2wT);

    const long long Z = 0;
    dim3 tb(32, 8);

    // 1. fused LayerNorms + emb pack
    ln_fused_kernel<<<BN_, 256>>>(emb[0], emb[1], emb[2], emb[3], lag, lab, lcg, lcb, cx, ec);
    pack_emb<<<dim3((BNE_+255)/256, 4), 256>>>(emb[0], emb[1], emb[2], emb[3], embA);

    // 2. weight transposes — batched big squares
    transpose4_sq<<<dim3(64,64,4), tb>>>(Wq, Wk, Wv, Wo,
                                         Wqkv, Wqkv + (long long)C_*C_, Wqkv + 2LL*C_*C_, WoT, C_);
    transpose4_sq<<<dim3(25,25,2), tb>>>(k_w, v_w, k_w, k_w,
                                         kvwT, kvwT + (long long)FN_*FN_, kvwT, kvwT, FN_);
    transpose_t<float,__half><<<dim3(7,7,4),   tb>>>(q_w, qwT, N_, N_, LP_, (long long)N_*N_, (long long)N_*LP_);
    transpose_t<float,__half><<<dim3(16,16,4), tb>>>(outw, outwT, E_, E_, E_, (long long)E_*E_, (long long)E_*E_);
    transpose_t<float,__half><<<dim3(64,16,4), tb>>>(fc1w, fc1wT, E_, 2048, E_, (long long)E_*2048, (long long)2048*E_);
    transpose_t<float,__half><<<dim3(16,64,4), tb>>>(fc2w, fc2wT, 2048, E_, 2048, (long long)2048*E_, (long long)E_*2048);
    transpose_t<__half,__half><<<dim3(16,7,64), tb>>>(cx, cxT, N_, E_, LP_, (long long)NE_, (long long)E_*LP_);

    // 3. channel projections merged QKV: G1 @2CTA, 1200 CTAs
    {
        dim3 g(16, 25, 3);
        G1<<<g,256,SM1>>>(BN_, C_, C_, ec, C_, Wqkv, C_, qkv, C_, nullptr, nullptr, 0, 1, 1.f,
                          3, 1,
                          Z, Z, Z,
                          (long long)C_*C_, Z, Z,
                          (long long)BN_*C_, Z, Z,
                          Z, Z, nullptr);
    }
    transpose_t<__half,__half><<<dim3(64,7,16), tb>>>(qkv + 2LL*BN_*C_, vcT, N_, C_, LP_,
                                                      (long long)N_*C_, (long long)C_*LP_);

    // 4. channel scores per (h,b): fp32 logits (G1 @2CTA)
    {
        dim3 g(2, 2, B_*H_);
        G1<<<g,256,SM1>>>(N_, N_, HDC_, qkv, C_, qkv + (long long)BN_*C_, C_, sch, N_,
                          nullptr, nullptr, 0, 0, 0.0625f,
                          H_, B_,
                          256LL, (long long)N_*C_, Z,
                          256LL, (long long)N_*C_, Z,
                          (long long)SCHZ_, (long long)H_*SCHZ_, Z,
                          Z, Z, nullptr);
    }
    // 5. channel softmax -> half probs
    softmax_fix<1,false,float><<<B_*H_*N_, 256>>>(sch, schh, N_, LP_, 1, nullptr, 1.f);

    // 6. T = s @ v per (h,b) (G2 — K=196 keeps wide-N reuse)
    {
        dim3 g(1, 2, B_*H_);
        G2<<<g,256,SM2>>>(N_, HDC_, N_, schh, LP_, vcT, LP_, tbuf, C_, nullptr, nullptr, 0, 1, 1.f,
                          H_, B_,
                          (long long)N_*LP_, (long long)H_*N_*LP_, Z,
                          (long long)256*LP_, (long long)C_*LP_, Z,
                          256LL, (long long)N_*C_, Z,
                          Z, Z, nullptr);
    }
    // 7. T_hat = T @ Wo: G1 @2CTA, 400 CTAs
    {
        dim3 g(16, 25, 1);
        G1<<<g,256,SM1>>>(BN_, C_, C_, tbuf, C_, WoT, C_, that, C_, nullptr, nullptr, 0, 1, 1.f,
                          1,1, Z,Z,Z, Z,Z,Z, Z,Z,Z, Z,Z, nullptr);
    }
    // 8. fused KV_S reshape + transpose
    kvsT_kernel<<<dim3(16, 7, 64), tb>>>(that, kvsT);

    // 9. K/V token-mix merged: G1 @2CTA, 896 CTAs
    {
        dim3 g(4, 7, 2*B_);
        G1<<<g,256,SM1>>>(FN_, E_, FN_, kvwT, FN_, kvsT, FN_, KV, E_, nullptr, nullptr, 0, 1, 1.f,
                          2, B_,
                          (long long)FN_*FN_, Z, Z,
                          Z, (long long)E_*FN_, Z,
                          (long long)B_*FNE_, (long long)FNE_, Z,
                          Z, Z, nullptr);
    }
    transpose_t<__half,__half><<<dim3(16,25,16), tb>>>(KV + (long long)B_*FNE_, VT, FN_, E_, FN_,
                                                       (long long)FNE_, (long long)E_*FN_);

    // 10. Q token-mix per (b,g) (G2 — K=196)
    {
        dim3 g(2, 2, 4*B_);
        G2<<<g,256,SM2>>>(N_, E_, N_, qwT, LP_, cxT, LP_, Qb, E_, nullptr, nullptr, 0, 1, 1.f,
                          B_, 4,
                          Z, (long long)N_*LP_, Z,
                          (long long)E_*LP_, (long long)B_*E_*LP_, Z,
                          (long long)NE_, (long long)BNE_, Z,
                          Z, Z, nullptr);
    }
    // 11. spatial logits per (h,b,g): HALF logits + fused fp32 stats partials (G1 @2CTA)
    {
        dim3 g(7, 2, 512);
        G1<<<g,256,SM1>>>(N_, FN_, HD_, Qb, E_, KV, E_, attnL, FN_, nullptr, nullptr, 0, 1, 1.f,
                          H_, B_,
                          64LL, (long long)NE_,  (long long)BNE_,
                          64LL, (long long)FNE_, Z,
                          (long long)ATTZ_, (long long)H_*ATTZ_, (long long)B_*H_*ATTZ_,
                          Z, Z, parts);
    }
    // 12-13. rstd + normalized softmax (half logits in, half probs out)
    rstd_parts<<<512, 32>>>(parts, rstdp, 14);
    softmax_fix<4,true,__half><<<512*N_, 256>>>(attnL, attnh, FN_, FN_, N_, rstdp, 1.f);

    // 14. ctx = p @ Vh per (h,b,g) -> cm (G3 @2CTA)
    {
        dim3 g(1, 2, 512);
        G3<<<g,256,SM3>>>(N_, HD_, FN_, attnh, FN_, VT, FN_, cm, HD_, nullptr, nullptr, 0, 1, 1.f,
                          H_, B_,
                          (long long)ATTZ_, (long long)H_*ATTZ_, (long long)B_*H_*ATTZ_,
                          (long long)HD_*FN_, (long long)E_*FN_, Z,
                          (long long)N_*HD_, (long long)H_*N_*HD_, (long long)BNE_,
                          Z, Z, nullptr);
    }
    // 15. branch-0 head permute -> slot 0
    merge0_kernel<<<(BN_*E_ + 255)/256, 256>>>(cm, ctx0);
    copy_half8<<<(BNE_/8 + 255)/256, 256>>>(ctx0, cm, BNE_/8);

    // 16. out projection + residual-1 merged over g: G1 @2CTA, 400 CTAs
    {
        dim3 g(4, 25, 4);
        G1<<<g,256,SM1>>>(BN_, E_, E_, cm, E_, outwT, E_, hbuf, E_,
                          nullptr, embA, 0, 0, 1.f,
                          4, 1,
                          (long long)BNE_, Z, Z,
                          (long long)E_*E_, Z, Z,
                          (long long)BNE_, Z, Z,
                          Z, (long long)BNE_, nullptr);
    }
    // 17. FFN LayerNorm
    ln_rows_kernel<<<4*BN_, 256>>>(hbuf, lfg, lfb, xln, BN_);

    // 18. fc1 + bias + GELU per g: G1 @2CTA, 1600 CTAs
    {
        dim3 g(16, 25, 4);
        G1<<<g,256,SM1>>>(BN_, 4*E_, E_, xln, E_, fc1wT, E_, x1, 4*E_,
                          fc1b, nullptr, 1, 1, 1.f,
                          4, 1,
                          (long long)BNE_, Z, Z,
                          (long long)2048*E_, Z, Z,
                          (long long)BN_*2048, Z, Z,
                          (long long)2048, Z, nullptr);
    }
    // 19. fc2 + bias + residual-2 -> out: G1 @2CTA, 400 CTAs
    {
        dim3 g(4, 25, 4);
        G1<<<g,256,SM1>>>(BN_, E_, 4*E_, x1, 4*E_, fc2wT, 4*E_, out, E_,
                          fc2b, hbuf, 0, 0, 1.f,
                          4, 1,
                          (long long)BN_*2048, Z, Z,
                          (long long)E_*2048, Z, Z,
                          (long long)BNE_, Z, Z,
                          (long long)E_, (long long)BNE_, nullptr);
    }
}

// round 15
// speedup vs baseline: 1.1685x; 1.0136x over previous
#include <cuda_runtime.h>
#include <cuda_fp16.h>
#include <cstdint>
#include <math.h>

#define B_     16
#define N_     196
#define E_     512
#define H_     8
#define HD_    64
#define C_     2048
#define HDC_   256
#define FN_    784
#define BN_    3136
#define NE_    100352
#define FNE_   401408
#define BNE_   1605632
#define SCHZ_  38416
#define ATTZ_  153664
#define LP_    200

// ---------------- scratch ----------------
__device__ __align__(128) __half h_cx  [4*BN_*E_];
__device__ __align__(128) __half h_cxT [4*B_*E_*LP_];
__device__ __align__(128) __half h_ec  [BN_*C_];
__device__ __align__(128) __half h_qkv [3LL*BN_*C_];
__device__ __align__(128) __half h_vcT [B_*C_*LP_];
__device__ __align__(128) float  g_sch [B_*H_*N_*N_];
__device__ __align__(128) __half h_sch [B_*H_*N_*LP_];
__device__ __align__(128) __half h_t   [BN_*C_];
__device__ __align__(128) __half h_that[BN_*C_];
__device__ __align__(128) __half h_kvsT[B_*E_*FN_];
__device__ __align__(128) __half h_KV  [2*B_*FN_*E_];
__device__ __align__(128) __half h_VT  [B_*E_*FN_];
__device__ __align__(128) __half h_Q   [4*BN_*E_];
__device__ __align__(128) __half h_attnL[512u*196*784];
__device__ __align__(128) __half h_attn [512u*196*784];
__device__ __align__(128) float  g_parts[512*14*2];
__device__ __align__(128) float  g_rstd[512];
__device__ __align__(128) __half h_cm  [4LL*BNE_];
__device__ __align__(128) __half h_ctx0[BNE_];
__device__ __align__(128) float  g_embA[4LL*BNE_];
__device__ __align__(128) float  g_h   [4*BN_*E_];
__device__ __align__(128) __half h_xln [4*BN_*E_];
__device__ __align__(128) __half h_x1  [4*BN_*2048];
__device__ __align__(128) __half h_qwT [4*N_*LP_];
__device__ __align__(128) __half h_kvwT[2*FN_*FN_];
__device__ __align__(128) __half h_Wqkv[3LL*C_*C_];
__device__ __align__(128) __half h_WoT [C_*C_];
__device__ __align__(128) __half h_outwT[4*E_*E_];
__device__ __align__(128) __half h_fc1wT[4*2048*E_];
__device__ __align__(128) __half h_fc2wT[4*E_*2048];

// ---------------- helpers ----------------
__device__ __forceinline__ uint32_t smem_u32(const void* p) {
    uint32_t a;
    asm("{ .reg .u64 t; cvta.to.shared.u64 t, %1; cvt.u32.u64 %0, t; }" : "=r"(a) : "l"(p));
    return a;
}
__device__ __forceinline__ void mma_f16(float* d, const uint32_t* a, const uint32_t* b) {
    asm volatile(
        "mma.sync.aligned.m16n8k16.row.col.f32.f16.f16.f32 "
        "{%0,%1,%2,%3}, {%4,%5,%6,%7}, {%8,%9}, {%0,%1,%2,%3};"
        : "+f"(d[0]), "+f"(d[1]), "+f"(d[2]), "+f"(d[3])
        : "r"(a[0]), "r"(a[1]), "r"(a[2]), "r"(a[3]), "r"(b[0]), "r"(b[1]));
}
__device__ __forceinline__ float gelu_f(float v) {
    return 0.5f * v * (1.f + erff(v * 0.70710678118654752f));
}
__device__ __forceinline__ void cpa16(uint32_t dst, const __half* src, int bytes) {
    asm volatile("cp.async.ca.shared.global [%0], [%1], 16, %2;"
                 :: "r"(dst), "l"(src), "r"(bytes) : "memory");
}
#define CP_COMMIT() asm volatile("cp.async.commit_group;" ::: "memory")
#define CP_WAIT1()  asm volatile("cp.async.wait_group 1;" ::: "memory")

// ---------------- reductions ----------------
__device__ __forceinline__ float block_sum(float v, float* sh) {
    int tid = threadIdx.x;
    #pragma unroll
    for (int o = 16; o > 0; o >>= 1) v += __shfl_down_sync(0xffffffffu, v, o);
    if ((tid & 31) == 0) sh[tid >> 5] = v;
    __syncthreads();
    if (tid < 32) {
        float t = (tid < (int)(blockDim.x >> 5)) ? sh[tid] : 0.f;
        #pragma unroll
        for (int o = 16; o > 0; o >>= 1) t += __shfl_down_sync(0xffffffffu, t, o);
        if (tid == 0) sh[0] = t;
    }
    __syncthreads();
    float r = sh[0];
    __syncthreads();
    return r;
}
__device__ __forceinline__ float block_max(float v, float* sh) {
    int tid = threadIdx.x;
    #pragma unroll
    for (int o = 16; o > 0; o >>= 1) v = fmaxf(v, __shfl_down_sync(0xffffffffu, v, o));
    if ((tid & 31) == 0) sh[tid >> 5] = v;
    __syncthreads();
    if (tid < 32) {
        float t = (tid < (int)(blockDim.x >> 5)) ? sh[tid] : -INFINITY;
        #pragma unroll
        for (int o = 16; o > 0; o >>= 1) t = fmaxf(t, __shfl_down_sync(0xffffffffu, t, o));
        if (tid == 0) sh[0] = t;
    }
    __syncthreads();
    float r = sh[0];
    __syncthreads();
    return r;
}

// ---------------- LN ----------------
__global__ void __launch_bounds__(256) ln_fused_kernel(
    const float* __restrict__ e1, const float* __restrict__ e2,
    const float* __restrict__ e3, const float* __restrict__ e4,
    const float* __restrict__ lag, const float* __restrict__ lab,
    const float* __restrict__ lcg, const float* __restrict__ lcb,
    __half* __restrict__ cx, __half* __restrict__ ec)
{
    __shared__ float sh[32];
    int token = blockIdx.x;
    int tid = threadIdx.x;
    const float* es[4] = {e1, e2, e3, e4};
    float x[4][2], mg[4], rg[4];
    float stot = 0.f, sstot = 0.f;
    #pragma unroll
    for (int g = 0; g < 4; g++) {
        const float* p = es[g] + (long long)token * E_;
        x[g][0] = p[tid]; x[g][1] = p[tid + 256];
        float s  = block_sum(x[g][0] + x[g][1], sh);
        float ss = block_sum(x[g][0]*x[g][0] + x[g][1]*x[g][1], sh);
        float m = s * (1.f/512.f);
        float v = ss * (1.f/512.f) - m*m;
        mg[g] = m; rg[g] = rsqrtf(v + 1e-6f);
        stot += s; sstot += ss;
    }
    float m = stot * (1.f/2048.f);
    float r = rsqrtf(sstot * (1.f/2048.f) - m*m + 1e-6f);
    #pragma unroll
    for (int g = 0; g < 4; g++) {
        #pragma unroll
        for (int j = 0; j < 2; j++) {
            int e = tid + j*256;
            float xv = x[g][j];
            cx[((long long)g*BN_ + token)*E_ + e] =
                __float2half_rn((xv - mg[g]) * rg[g] * lag[g*E_+e] + lab[g*E_+e]);
            ec[(long long)token*C_ + g*E_ + e] =
                __float2half_rn((xv - m) * r * lcg[g*E_+e] + lcb[g*E_+e]);
        }
    }
}

__global__ void __launch_bounds__(256) ln_rows_kernel(
    const float* __restrict__ X, const float* __restrict__ gamma,
    const float* __restrict__ beta, __half* __restrict__ Y, int rowsPerG)
{
    __shared__ float sh[32];
    long long row = blockIdx.x;
    int tid = threadIdx.x;
    int g = (int)(row / rowsPerG);
    const float* p = X + row * E_;
    float x0 = p[tid], x1 = p[tid+256];
    float s  = block_sum(x0 + x1, sh);
    float ss = block_sum(x0*x0 + x1*x1, sh);
    float m = s * (1.f/512.f);
    float r = rsqrtf(ss * (1.f/512.f) - m*m + 1e-6f);
    __half* q = Y + row * E_;
    q[tid]     = __float2half_rn((x0 - m) * r * gamma[g*E_+tid]     + beta[g*E_+tid]);
    q[tid+256] = __float2half_rn((x1 - m) * r * gamma[g*E_+tid+256] + beta[g*E_+tid+256]);
}

// ---------------- rstd from per-CTA partials ----------------
__global__ void rstd_parts(const float* __restrict__ parts, float* __restrict__ rstd, int nparts) {
    int z = blockIdx.x;
    int t = threadIdx.x;
    float s = 0.f, q = 0.f;
    if (t < nparts) { s = parts[(z*nparts+t)*2]; q = parts[(z*nparts+t)*2+1]; }
    #pragma unroll
    for (int o = 16; o > 0; o >>= 1) {
        s += __shfl_down_sync(0xffffffffu, s, o);
        q += __shfl_down_sync(0xffffffffu, q, o);
    }
    if (t == 0) {
        float m = s * (1.f/(float)ATTZ_);
        rstd[z] = rsqrtf(q * (1.f/(float)ATTZ_) - m*m + 1e-5f);
    }
}

// ---------------- softmax: TI logits -> half probs ----------------
template<int NIT, bool PERZ, typename TI>
__global__ void __launch_bounds__(256) softmax_fix(
    const TI* __restrict__ S, __half* __restrict__ O,
    int cols, int ldo, int rowsPerZ,
    const float* __restrict__ rstd, float scale)
{
    __shared__ float sh[32];
    long long row = blockIdx.x;
    const TI* p = S + row * cols;
    __half* q = O + row * ldo;
    float sc = PERZ ? rstd[(int)(row / rowsPerZ)] : scale;
    int tid = threadIdx.x;
    float vals[NIT];
    float mx = -INFINITY;
    #pragma unroll
    for (int it = 0; it < NIT; it++) {
        int i = tid + it*256;
        float t = (i < cols) ? (float)p[i]*sc : -INFINITY;
        vals[it] = t;
        mx = fmaxf(mx, t);
    }
    mx = block_max(mx, sh);
    float s = 0.f;
    #pragma unroll
    for (int it = 0; it < NIT; it++) {
        float e = expf(vals[it] - mx);
        vals[it] = e;
        s += e;
    }
    s = block_sum(s, sh);
    float inv = 1.f / s;
    #pragma unroll
    for (int it = 0; it < NIT; it++) {
        int i = tid + it*256;
        if (i < cols) q[i] = __float2half_rn(vals[it] * inv);
    }
}

// ---------------- tiled transpose ----------------
template<typename TI, typename TO>
__global__ void transpose_t(const TI* __restrict__ in, TO* __restrict__ out,
                            int R, int Cc, int ldo, long long zi, long long zo)
{
    __shared__ float t[32][33];
    const TI* ip = in + (long long)blockIdx.z * zi;
    TO* op = out + (long long)blockIdx.z * zo;
    int c0 = blockIdx.x*32, r0 = blockIdx.y*32;
    int x = threadIdx.x, y = threadIdx.y;
    #pragma unroll
    for (int j = 0; j < 32; j += 8) {
        int r = r0 + y + j, c = c0 + x;
        if (r < R && c < Cc) t[y+j][x] = (float)ip[(long long)r*Cc + c];
    }
    __syncthreads();
    #pragma unroll
    for (int j = 0; j < 32; j += 8) {
        int c = c0 + y + j, r = r0 + x;
        if (r < R && c < Cc) op[(long long)c*ldo + r] = (TO)t[x][y+j];
    }
}

__global__ void transpose4_sq(const float* __restrict__ p0, const float* __restrict__ p1,
                              const float* __restrict__ p2, const float* __restrict__ p3,
                              __half* __restrict__ o0, __half* __restrict__ o1,
                              __half* __restrict__ o2, __half* __restrict__ o3, int D)
{
    __shared__ float t[32][33];
    int zi = blockIdx.z;
    const float* ip = (zi == 0) ? p0 : (zi == 1) ? p1 : (zi == 2) ? p2 : p3;
    __half* op = (zi == 0) ? o0 : (zi == 1) ? o1 : (zi == 2) ? o2 : o3;
    int c0 = blockIdx.x*32, r0 = blockIdx.y*32;
    int x = threadIdx.x, y = threadIdx.y;
    #pragma unroll
    for (int j = 0; j < 32; j += 8) {
        int r = r0 + y + j, c = c0 + x;
        if (r < D && c < D) t[y+j][x] = ip[(long long)r*D + c];
    }
    __syncthreads();
    #pragma unroll
    for (int j = 0; j < 32; j += 8) {
        int c = c0 + y + j, r = r0 + x;
        if (r < D && c < D) op[(long long)c*D + r] = (__half)t[x][y+j];
    }
}

__global__ void kvsT_kernel(const __half* __restrict__ that, __half* __restrict__ kvsT)
{
    __shared__ __half t[32][34];
    int g = blockIdx.z & 3, b = blockIdx.z >> 2;
    int n0 = blockIdx.y*32, e0 = blockIdx.x*32;
    const __half* in = that + (long long)b*N_*C_ + g*E_;
    __half* out = kvsT + (long long)b*E_*FN_ + g*N_;
    int x = threadIdx.x, y = threadIdx.y;
    #pragma unroll
    for (int j = 0; j < 32; j += 8) {
        int n = n0 + y + j;
        if (n < N_) t[y+j][x] = in[(long long)n*C_ + e0 + x];
    }
    __syncthreads();
    #pragma unroll
    for (int j = 0; j < 32; j += 8) {
        int n = n0 + x;
        if (n < N_) out[(long long)(e0+y+j)*FN_ + n] = t[x][y+j];
    }
}

__global__ void merge0_kernel(const __half* __restrict__ cm, __half* __restrict__ ctx0) {
    int idx = blockIdx.x * blockDim.x + threadIdx.x;
    if (idx >= BN_*E_) return;
    int b = idx / NE_;
    int rem = idx % NE_;
    int n = rem / E_;
    int e = rem % E_;
    int h = e >> 6, d = e & 63;
    ctx0[idx] = cm[((long long)(b*H_ + h)*N_ + n)*HD_ + d];
}

__global__ void copy_half8(const __half* __restrict__ src, __half* __restrict__ dst, int n8) {
    int i = blockIdx.x * blockDim.x + threadIdx.x;
    if (i < n8) ((uint4*)dst)[i] = ((const uint4*)src)[i];
}

__global__ void pack_emb(const float* __restrict__ e1, const float* __restrict__ e2,
                         const float* __restrict__ e3, const float* __restrict__ e4,
                         float* __restrict__ out) {
    const float* es[4] = {e1, e2, e3, e4};
    int g = blockIdx.y;
    int i = blockIdx.x * blockDim.x + threadIdx.x;
    if (i < BNE_) out[(long long)g*BNE_ + i] = es[g][i];
}

// ---------------- fp16 mma.sync GEMM (R7 mainloop) + optional fused stats ----------------
__device__ __forceinline__ void epi_store(
    void* __restrict__ Cv, const float* __restrict__ bias, const float* __restrict__ res,
    int ldc, int row, int gc, int M, int act, int outHalf, float alpha, float c0, float c1)
{
    if (row >= M) return;
    float2 v = make_float2(c0*alpha, c1*alpha);
    if (bias) { v.x += bias[gc]; v.y += bias[gc+1]; }
    if (act)  { v.x = gelu_f(v.x); v.y = gelu_f(v.y); }
    if (res)  { float2 rr = *(const float2*)(res + (long long)row*ldc + gc);
                v.x += rr.x; v.y += rr.y; }
    if (outHalf) {
        *(__half2*)((__half*)Cv + (long long)row*ldc + gc) = __floats2half2_rn(v.x, v.y);
    } else {
        *(float2*)((float*)Cv + (long long)row*ldc + gc) = v;
    }
}

template<int TM, int TN, int WM, int WN, int MINB>
__global__ void __launch_bounds__(256, MINB) gemm_h(
    int M, int Ncol, int K,
    const __half* __restrict__ A, int lda,
    const __half* __restrict__ B, int ldb,
    void* __restrict__ Cv, int ldc,
    const float* __restrict__ bias,
    const float* __restrict__ res,
    int act, int outHalf, float alpha,
    int D0, int D1,
    long long sA0, long long sA1, long long sA2,
    long long sB0, long long sB1, long long sB2,
    long long sC0, long long sC1, long long sC2,
    long long sBias0, long long sR0,
    float* __restrict__ sout)
{
    constexpr int WMS = TM / WM;
    constexpr int MI  = WM / 16;
    constexpr int NJ  = WN / 8;
    constexpr int ABUFW = TM * 32;
    constexpr int BBUFW = TN * 32;
    constexpr int ASLOT = (TM*2 + 255) / 256;
    constexpr int BSLOT = (TN*2 + 255) / 256;

    long long z = blockIdx.z;
    int z0 = (int)(z % D0); long long t = z / D0;
    int z1 = (int)(t % D1); int z2 = (int)(t / D1);
    A += z0*sA0 + z1*sA1 + z2*sA2;
    B += z0*sB0 + z1*sB1 + z2*sB2;
    long long coff = z0*sC0 + z1*sC1 + z2*sC2;
    Cv = outHalf ? (void*)((__half*)Cv + coff) : (void*)((float*)Cv + coff);
    if (bias) bias += z0*sBias0;
    if (res)  res  += z0*sR0;

    extern __shared__ uint32_t smw[];
    uint32_t* As = smw;
    uint32_t* Bs = smw + 2*ABUFW;

    int tid = threadIdx.x;
    int lane = tid & 31;
    int wid = tid >> 5;
    int warp_m = wid % WMS;
    int warp_n = wid / WMS;
    int row0 = blockIdx.y * TM;
    int col0 = blockIdx.x * TN;

    float acc[MI][NJ][4];
    #pragma unroll
    for (int i = 0; i < MI; i++)
        #pragma unroll
        for (int j = 0; j < NJ; j++)
            #pragma unroll
            for (int q = 0; q < 4; q++) acc[i][j][q] = 0.f;

    const __half* aPtr[ASLOT]; uint32_t aOff[ASLOT][4]; int aKh[ASLOT]; bool aV[ASLOT];
    const __half* bPtr[BSLOT]; uint32_t bOff[BSLOT][4]; int bKh[BSLOT]; bool bV[BSLOT];
    #pragma unroll
    for (int i = 0; i < ASLOT; i++) {
        int sidx = tid + i*256;
        bool inA = sidx < TM*2;
        int r = inA ? (sidx >> 1) : 0;
        int khw = (sidx & 1) * 16;
        aKh[i] = (sidx & 1) * 32;
        bool val = inA && (row0 + r) < M;
        aV[i] = val;
        aPtr[i] = A + (long long)(val ? row0 + r : 0) * lda;
        int sw = (r & 7) << 2;
        #pragma unroll
        for (int j = 0; j < 4; j++)
            aOff[i][j] = (uint32_t)((r*32 + ((khw + j*4) ^ sw)) << 2);
    }
    #pragma unroll
    for (int i = 0; i < BSLOT; i++) {
        int sidx = tid + i*256;
        bool inB = sidx < TN*2;
        int r = inB ? (sidx >> 1) : 0;
        int khw = (sidx & 1) * 16;
        bKh[i] = (sidx & 1) * 32;
        bool val = inB && (col0 + r) < Ncol;
        bV[i] = val;
        bPtr[i] = B + (long long)(val ? col0 + r : 0) * ldb;
        int sw = (r & 7) << 2;
        #pragma unroll
        for (int j = 0; j < 4; j++)
            bOff[i][j] = (uint32_t)((r*32 + ((khw + j*4) ^ sw)) << 2);
    }

    uint32_t aSm = smem_u32(As);
    uint32_t bSm = smem_u32(Bs);
    int KT = (K + 63) >> 6;
    int lr = lane >> 2;
    int lc = lane & 3;

    // prologue -> buffer 0
    #pragma unroll
    for (int i = 0; i < ASLOT; i++) {
        if ((ASLOT > 1) && (tid + i*256 >= TM*2)) continue;
        #pragma unroll
        for (int j = 0; j < 4; j++) {
            int gk = aKh[i] + j*8;
            int nb = (K - gk) * 2; nb = nb < 0 ? 0 : (nb > 16 ? 16 : nb);
            int ba = aV[i] ? nb : 0;
            cpa16(aSm + aOff[i][j], aPtr[i] + (ba ? gk : 0), ba);
        }
    }
    #pragma unroll
    for (int i = 0; i < BSLOT; i++) {
        if (tid + i*256 >= TN*2) continue;
        #pragma unroll
        for (int j = 0; j < 4; j++) {
            int gk = bKh[i] + j*8;
            int nb = (K - gk) * 2; nb = nb < 0 ? 0 : (nb > 16 ? 16 : nb);
            int bb = bV[i] ? nb : 0;
            cpa16(bSm + bOff[i][j], bPtr[i] + (bb ? gk : 0), bb);
        }
    }
    CP_COMMIT();

    for (int kt = 0; kt < KT; kt++) {
        int p = kt & 1;
        __syncthreads();
        if (kt + 1 < KT) {
            uint32_t aBo = (uint32_t)((1 - p) * ABUFW * 4);
            uint32_t bBo = (uint32_t)((1 - p) * BBUFW * 4);
            int k0 = (kt+1)*64;
            #pragma unroll
            for (int i = 0; i < ASLOT; i++) {
                if ((ASLOT > 1) && (tid + i*256 >= TM*2)) continue;
                #pragma unroll
                for (int j = 0; j < 4; j++) {
                    int gk = k0 + aKh[i] + j*8;
                    int nb = (K - gk) * 2; nb = nb < 0 ? 0 : (nb > 16 ? 16 : nb);
                    int ba = aV[i] ? nb : 0;
                    cpa16(aSm + aBo + aOff[i][j], aPtr[i] + (ba ? gk : 0), ba);
                }
            }
            #pragma unroll
            for (int i = 0; i < BSLOT; i++) {
                if (tid + i*256 >= TN*2) continue;
                #pragma unroll
                for (int j = 0; j < 4; j++) {
                    int gk = k0 + bKh[i] + j*8;
                    int nb = (K - gk) * 2; nb = nb < 0 ? 0 : (nb > 16 ? 16 : nb);
                    int bb = bV[i] ? nb : 0;
                    cpa16(bSm + bBo + bOff[i][j], bPtr[i] + (bb ? gk : 0), bb);
                }
            }
        }
        CP_COMMIT();
        CP_WAIT1();
        __syncthreads();

        const uint32_t* Ab = As + p*ABUFW;
        const uint32_t* Bb = Bs + p*BBUFW;
        #pragma unroll
        for (int ks = 0; ks < 4; ks++) {
            int w0 = ks*8 + lc;
            int w1 = w0 + 4;
            uint32_t af[MI][4], bf[NJ][2];
            #pragma unroll
            for (int i = 0; i < MI; i++) {
                int m = warp_m*WM + i*16 + lr;
                int s = (m & 7) << 2;
                af[i][0] = Ab[m*32 + (w0 ^ s)];
                af[i][1] = Ab[(m+8)*32 + (w0 ^ s)];
                af[i][2] = Ab[m*32 + (w1 ^ s)];
                af[i][3] = Ab[(m+8)*32 + (w1 ^ s)];
            }
            #pragma unroll
            for (int j = 0; j < NJ; j++) {
                int n = warp_n*WN + j*8 + lr;
                int s = (n & 7) << 2;
                bf[j][0] = Bb[n*32 + (w0 ^ s)];
                bf[j][1] = Bb[n*32 + (w1 ^ s)];
            }
            #pragma unroll
            for (int i = 0; i < MI; i++)
                #pragma unroll
                for (int j = 0; j < NJ; j++)
                    mma_f16(acc[i][j], af[i], bf[j]);
        }
    }

    #pragma unroll
    for (int i = 0; i < MI; i++) {
        int gr = row0 + warp_m*WM + i*16 + lr;
        #pragma unroll
        for (int j = 0; j < NJ; j++) {
            int gc = col0 + warp_n*WN + j*8 + lc*2;
            if (gc >= Ncol) continue;
            epi_store(Cv, bias, res, ldc, gr,   gc, M, act, outHalf, alpha, acc[i][j][0], acc[i][j][1]);
            epi_store(Cv, bias, res, ldc, gr+8, gc, M, act, outHalf, alpha, acc[i][j][2], acc[i][j][3]);
        }
    }

    if (sout) {
        float s = 0.f, q = 0.f;
        #pragma unroll
        for (int i = 0; i < MI; i++)
            #pragma unroll
            for (int j = 0; j < NJ; j++)
                #pragma unroll
                for (int qq = 0; qq < 4; qq++) {
                    float v = acc[i][j][qq];
                    s += v; q += v*v;
                }
        #pragma unroll
        for (int o = 16; o > 0; o >>= 1) {
            s += __shfl_down_sync(0xffffffffu, s, o);
            q += __shfl_down_sync(0xffffffffu, q, o);
        }
        float* shf = (float*)smw;
        __syncthreads();
        if (lane == 0) { shf[wid] = s; shf[8 + wid] = q; }
        __syncthreads();
        if (tid == 0) {
            float ts = 0.f, tq = 0.f;
            #pragma unroll
            for (int w = 0; w < 8; w++) { ts += shf[w]; tq += shf[8 + w]; }
            long long cid = (long long)blockIdx.z * (gridDim.x * gridDim.y)
                          + blockIdx.y * gridDim.x + blockIdx.x;
            sout[cid*2]   = ts;
            sout[cid*2+1] = tq;
        }
    }
}

// ---------------- host ----------------
static void* symaddr(const void* sym) {
    void* p = nullptr;
    cudaGetSymbolAddress(&p, sym);
    return p;
}

#define G1 gemm_h<128,128,64,32,2>
#define G3 gemm_h<128,64,32,32,2>
#define SM1 65536
#define SM3 49152

extern "C" void kernel_launch(void* const* d_in, const int* in_sizes, int n_in,
                              void* d_out, int out_size) {
    const float* emb[4] = {(const float*)d_in[0], (const float*)d_in[1],
                           (const float*)d_in[2], (const float*)d_in[3]};
    const float* lag  = (const float*)d_in[4];
    const float* lab  = (const float*)d_in[5];
    const float* lcg  = (const float*)d_in[6];
    const float* lcb  = (const float*)d_in[7];
    const float* Wq   = (const float*)d_in[8];
    const float* Wk   = (const float*)d_in[9];
    const float* Wv   = (const float*)d_in[10];
    const float* Wo   = (const float*)d_in[11];
    const float* q_w  = (const float*)d_in[12];
    const float* k_w  = (const float*)d_in[13];
    const float* v_w  = (const float*)d_in[14];
    const float* outw = (const float*)d_in[15];
    const float* lfg  = (const float*)d_in[16];
    const float* lfb  = (const float*)d_in[17];
    const float* fc1w = (const float*)d_in[18];
    const float* fc1b = (const float*)d_in[19];
    const float* fc2w = (const float*)d_in[20];
    const float* fc2b = (const float*)d_in[21];
    float* out = (float*)d_out;

    cudaFuncSetAttribute(G1, cudaFuncAttributeMaxDynamicSharedMemorySize, SM1);
    cudaFuncSetAttribute(G3, cudaFuncAttributeMaxDynamicSharedMemorySize, SM3);

    __half* cx   = (__half*)symaddr(h_cx);   __half* cxT  = (__half*)symaddr(h_cxT);
    __half* ec   = (__half*)symaddr(h_ec);
    __half* qkv  = (__half*)symaddr(h_qkv);  __half* vcT  = (__half*)symaddr(h_vcT);
    float*  sch  = (float*)symaddr(g_sch);   __half* schh = (__half*)symaddr(h_sch);
    __half* tbuf = (__half*)symaddr(h_t);    __half* that = (__half*)symaddr(h_that);
    __half* kvsT = (__half*)symaddr(h_kvsT);
    __half* KV   = (__half*)symaddr(h_KV);   __half* VT   = (__half*)symaddr(h_VT);
    __half* Qb   = (__half*)symaddr(h_Q);
    __half* attnL= (__half*)symaddr(h_attnL);__half* attnh= (__half*)symaddr(h_attn);
    float*  parts= (float*)symaddr(g_parts); float*  rstdp= (float*)symaddr(g_rstd);
    __half* cm   = (__half*)symaddr(h_cm);   __half* ctx0 = (__half*)symaddr(h_ctx0);
    float*  embA = (float*)symaddr(g_embA);
    float*  hbuf = (float*)symaddr(g_h);     __half* xln  = (__half*)symaddr(h_xln);
    __half* x1   = (__half*)symaddr(h_x1);
    __half* qwT  = (__half*)symaddr(h_qwT);  __half* kvwT = (__half*)symaddr(h_kvwT);
    __half* Wqkv = (__half*)symaddr(h_Wqkv); __half* WoT  = (__half*)symaddr(h_WoT);
    __half* outwT= (__half*)symaddr(h_outwT);
    __half* fc1wT= (__half*)symaddr(h_fc1wT);__half* fc2wT= (__half*)symaddr(h_fc2wT);

    const long long Z = 0;
    dim3 tb(32, 8);

    // 1. fused LayerNorms + emb pack
    ln_fused_kernel<<<BN_, 256>>>(emb[0], emb[1], emb[2], emb[3], lag, lab, lcg, lcb, cx, ec);
    pack_emb<<<dim3((BNE_+255)/256, 4), 256>>>(emb[0], emb[1], emb[2], emb[3], embA);

    // 2. weight transposes
    transpose4_sq<<<dim3(64,64,4), tb>>>(Wq, Wk, Wv, Wo,
                                         Wqkv, Wqkv + (long long)C_*C_, Wqkv + 2LL*C_*C_, WoT, C_);
    transpose4_sq<<<dim3(25,25,2), tb>>>(k_w, v_w, k_w, k_w,
                                         kvwT, kvwT + (long long)FN_*FN_, kvwT, kvwT, FN_);
    transpose_t<float,__half><<<dim3(7,7,4),   tb>>>(q_w, qwT, N_, N_, LP_, (long long)N_*N_, (long long)N_*LP_);
    transpose_t<float,__half><<<dim3(16,16,4), tb>>>(outw, outwT, E_, E_, E_, (long long)E_*E_, (long long)E_*E_);
    transpose_t<float,__half><<<dim3(64,16,4), tb>>>(fc1w, fc1wT, E_, 2048, E_, (long long)E_*2048, (long long)2048*E_);
    transpose_t<float,__half><<<dim3(16,64,4), tb>>>(fc2w, fc2wT, 2048, E_, 2048, (long long)2048*E_, (long long)E_*2048);
    transpose_t<__half,__half><<<dim3(16,7,64), tb>>>(cx, cxT, N_, E_, LP_, (long long)NE_, (long long)E_*LP_);

    // 3. channel projections merged QKV: G1 @2CTA
    {
        dim3 g(16, 25, 3);
        G1<<<g,256,SM1>>>(BN_, C_, C_, ec, C_, Wqkv, C_, qkv, C_, nullptr, nullptr, 0, 1, 1.f,
                          3, 1,
                          Z, Z, Z,
                          (long long)C_*C_, Z, Z,
                          (long long)BN_*C_, Z, Z,
                          Z, Z, nullptr);
    }
    transpose_t<__half,__half><<<dim3(64,7,16), tb>>>(qkv + 2LL*BN_*C_, vcT, N_, C_, LP_,
                                                      (long long)N_*C_, (long long)C_*LP_);

    // 4. channel scores per (h,b): fp32 logits (G1 @2CTA)
    {
        dim3 g(2, 2, B_*H_);
        G1<<<g,256,SM1>>>(N_, N_, HDC_, qkv, C_, qkv + (long long)BN_*C_, C_, sch, N_,
                          nullptr, nullptr, 0, 0, 0.0625f,
                          H_, B_,
                          256LL, (long long)N_*C_, Z,
                          256LL, (long long)N_*C_, Z,
                          (long long)SCHZ_, (long long)H_*SCHZ_, Z,
                          Z, Z, nullptr);
    }
    // 5. channel softmax -> half probs
    softmax_fix<1,false,float><<<B_*H_*N_, 256>>>(sch, schh, N_, LP_, 1, nullptr, 1.f);

    // 6. T = s @ v per (h,b): G1 @2CTA, 512 CTAs
    {
        dim3 g(2, 2, B_*H_);
        G1<<<g,256,SM1>>>(N_, HDC_, N_, schh, LP_, vcT, LP_, tbuf, C_, nullptr, nullptr, 0, 1, 1.f,
                          H_, B_,
                          (long long)N_*LP_, (long long)H_*N_*LP_, Z,
                          (long long)256*LP_, (long long)C_*LP_, Z,
                          256LL, (long long)N_*C_, Z,
                          Z, Z, nullptr);
    }
    // 7. T_hat = T @ Wo: G1 @2CTA
    {
        dim3 g(16, 25, 1);
        G1<<<g,256,SM1>>>(BN_, C_, C_, tbuf, C_, WoT, C_, that, C_, nullptr, nullptr, 0, 1, 1.f,
                          1,1, Z,Z,Z, Z,Z,Z, Z,Z,Z, Z,Z, nullptr);
    }
    // 8. fused KV_S reshape + transpose
    kvsT_kernel<<<dim3(16, 7, 64), tb>>>(that, kvsT);

    // 9. K/V token-mix merged: G1 @2CTA
    {
        dim3 g(4, 7, 2*B_);
        G1<<<g,256,SM1>>>(FN_, E_, FN_, kvwT, FN_, kvsT, FN_, KV, E_, nullptr, nullptr, 0, 1, 1.f,
                          2, B_,
                          (long long)FN_*FN_, Z, Z,
                          Z, (long long)E_*FN_, Z,
                          (long long)B_*FNE_, (long long)FNE_, Z,
                          Z, Z, nullptr);
    }
    transpose_t<__half,__half><<<dim3(16,25,16), tb>>>(KV + (long long)B_*FNE_, VT, FN_, E_, FN_,
                                                       (long long)FNE_, (long long)E_*FN_);

    // 10. Q token-mix per (b,g): G1 @2CTA, 512 CTAs
    {
        dim3 g(4, 2, 4*B_);
        G1<<<g,256,SM1>>>(N_, E_, N_, qwT, LP_, cxT, LP_, Qb, E_, nullptr, nullptr, 0, 1, 1.f,
                          B_, 4,
                          Z, (long long)N_*LP_, Z,
                          (long long)E_*LP_, (long long)B_*E_*LP_, Z,
                          (long long)NE_, (long long)BNE_, Z,
                          Z, Z, nullptr);
    }
    // 11. spatial logits per (h,b,g): HALF logits + fused fp32 stats partials (G1 @2CTA)
    {
        dim3 g(7, 2, 512);
        G1<<<g,256,SM1>>>(N_, FN_, HD_, Qb, E_, KV, E_, attnL, FN_, nullptr, nullptr, 0, 1, 1.f,
                          H_, B_,
                          64LL, (long long)NE_,  (long long)BNE_,
                          64LL, (long long)FNE_, Z,
                          (long long)ATTZ_, (long long)H_*ATTZ_, (long long)B_*H_*ATTZ_,
                          Z, Z, parts);
    }
    // 12-13. rstd + normalized softmax
    rstd_parts<<<512, 32>>>(parts, rstdp, 14);
    softmax_fix<4,true,__half><<<512*N_, 256>>>(attnL, attnh, FN_, FN_, N_, rstdp, 1.f);

    // 14. ctx = p @ Vh per (h,b,g) -> cm (G3 @2CTA)
    {
        dim3 g(1, 2, 512);
        G3<<<g,256,SM3>>>(N_, HD_, FN_, attnh, FN_, VT, FN_, cm, HD_, nullptr, nullptr, 0, 1, 1.f,
                          H_, B_,
                          (long long)ATTZ_, (long long)H_*ATTZ_, (long long)B_*H_*ATTZ_,
                          (long long)HD_*FN_, (long long)E_*FN_, Z,
                          (long long)N_*HD_, (long long)H_*N_*HD_, (long long)BNE_,
                          Z, Z, nullptr);
    }
    // 15. branch-0 head permute -> slot 0
    merge0_kernel<<<(BN_*E_ + 255)/256, 256>>>(cm, ctx0);
    copy_half8<<<(BNE_/8 + 255)/256, 256>>>(ctx0, cm, BNE_/8);

    // 16. out projection + residual-1 merged over g: G1 @2CTA
    {
        dim3 g(4, 25, 4);
        G1<<<g,256,SM1>>>(BN_, E_, E_, cm, E_, outwT, E_, hbuf, E_,
                          nullptr, embA, 0, 0, 1.f,
                          4, 1,
                          (long long)BNE_, Z, Z,
                          (long long)E_*E_, Z, Z,
                          (long long)BNE_, Z, Z,
                          Z, (long long)BNE_, nullptr);
    }
    // 17. FFN LayerNorm
    ln_rows_kernel<<<4*BN_, 256>>>(hbuf, lfg, lfb, xln, BN_);

    // 18. fc1 + bias + GELU per g: G1 @2CTA
    {
        dim3 g(16, 25, 4);
        G1<<<g,256,SM1>>>(BN_, 4*E_, E_, xln, E_, fc1wT, E_, x1, 4*E_,
                          fc1b, nullptr, 1, 1, 1.f,
                          4, 1,
                          (long long)BNE_, Z, Z,
                          (long long)2048*E_, Z, Z,
                          (long long)BN_*2048, Z, Z,
                          (long long)2048, Z, nullptr);
    }
    // 19. fc2 + bias + residual-2 -> out: G1 @2CTA
    {
        dim3 g(4, 25, 4);
        G1<<<g,256,SM1>>>(BN_, E_, 4*E_, x1, 4*E_, fc2wT, 4*E_, out, E_,
                          fc2b, hbuf, 0, 0, 1.f,
                          4, 1,
                          (long long)BN_*2048, Z, Z,
                          (long long)E_*2048, Z, Z,
                          (long long)BNE_, Z, Z,
                          (long long)E_, (long long)BNE_, nullptr);
    }
}

// round 17
// speedup vs baseline: 1.2227x; 1.0464x over previous
#include <cuda_runtime.h>
#include <cuda_fp16.h>
#include <cstdint>
#include <math.h>

#define B_     16
#define N_     196
#define E_     512
#define H_     8
#define HD_    64
#define C_     2048
#define HDC_   256
#define FN_    784
#define BN_    3136
#define NE_    100352
#define FNE_   401408
#define BNE_   1605632
#define SCHZ_  38416
#define ATTZ_  153664
#define LP_    200

// ---------------- scratch ----------------
__device__ __align__(128) __half h_cx  [4*BN_*E_];
__device__ __align__(128) __half h_cxT [4*B_*E_*LP_];
__device__ __align__(128) __half h_ec  [BN_*C_];
__device__ __align__(128) __half h_qkv [3LL*BN_*C_];
__device__ __align__(128) __half h_vcT [B_*C_*LP_];
__device__ __align__(128) float  g_sch [B_*H_*N_*N_];
__device__ __align__(128) __half h_sch [B_*H_*N_*LP_];
__device__ __align__(128) __half h_t   [BN_*C_];
__device__ __align__(128) __half h_that[BN_*C_];
__device__ __align__(128) __half h_kvsT[B_*E_*FN_];
__device__ __align__(128) __half h_KV  [2*B_*FN_*E_];
__device__ __align__(128) __half h_VT  [B_*E_*FN_];
__device__ __align__(128) __half h_Q   [4*BN_*E_];
__device__ __align__(128) __half h_attnL[512u*196*784];   // half logits
__device__ __align__(128) float  g_parts[512*14*2];
__device__ __align__(128) float  g_rstd[512];
__device__ __align__(128) __half h_cm  [4LL*BNE_];
__device__ __align__(128) __half h_ctx0[BNE_];
__device__ __align__(128) float  g_embA[4LL*BNE_];
__device__ __align__(128) float  g_h   [4*BN_*E_];
__device__ __align__(128) __half h_xln [4*BN_*E_];
__device__ __align__(128) __half h_x1  [4*BN_*2048];
__device__ __align__(128) __half h_qwT [4*N_*LP_];
__device__ __align__(128) __half h_kvwT[2*FN_*FN_];
__device__ __align__(128) __half h_Wqkv[3LL*C_*C_];
__device__ __align__(128) __half h_WoT [C_*C_];
__device__ __align__(128) __half h_outwT[4*E_*E_];
__device__ __align__(128) __half h_fc1wT[4*2048*E_];
__device__ __align__(128) __half h_fc2wT[4*E_*2048];

// ---------------- helpers ----------------
__device__ __forceinline__ uint32_t smem_u32(const void* p) {
    uint32_t a;
    asm("{ .reg .u64 t; cvta.to.shared.u64 t, %1; cvt.u32.u64 %0, t; }" : "=r"(a) : "l"(p));
    return a;
}
__device__ __forceinline__ void mma_f16(float* d, const uint32_t* a, const uint32_t* b) {
    asm volatile(
        "mma.sync.aligned.m16n8k16.row.col.f32.f16.f16.f32 "
        "{%0,%1,%2,%3}, {%4,%5,%6,%7}, {%8,%9}, {%0,%1,%2,%3};"
        : "+f"(d[0]), "+f"(d[1]), "+f"(d[2]), "+f"(d[3])
        : "r"(a[0]), "r"(a[1]), "r"(a[2]), "r"(a[3]), "r"(b[0]), "r"(b[1]));
}
__device__ __forceinline__ float gelu_f(float v) {
    return 0.5f * v * (1.f + erff(v * 0.70710678118654752f));
}
__device__ __forceinline__ void cpa16(uint32_t dst, const __half* src, int bytes) {
    asm volatile("cp.async.ca.shared.global [%0], [%1], 16, %2;"
                 :: "r"(dst), "l"(src), "r"(bytes) : "memory");
}
#define CP_COMMIT() asm volatile("cp.async.commit_group;" ::: "memory")
#define CP_WAIT1()  asm volatile("cp.async.wait_group 1;" ::: "memory")

__device__ __forceinline__ uint32_t exp_h2(uint32_t u, float rs, bool v, float& sum) {
    if (!v) return 0u;
    __half2 h = *(__half2*)&u;
    float fx = expf(__half2float(__low2half(h)) * rs);
    float fy = expf(__half2float(__high2half(h)) * rs);
    sum += fx + fy;
    __half2 r = __floats2half2_rn(fx, fy);
    return *(uint32_t*)&r;
}

// ---------------- reductions ----------------
__device__ __forceinline__ float block_sum(float v, float* sh) {
    int tid = threadIdx.x;
    #pragma unroll
    for (int o = 16; o > 0; o >>= 1) v += __shfl_down_sync(0xffffffffu, v, o);
    if ((tid & 31) == 0) sh[tid >> 5] = v;
    __syncthreads();
    if (tid < 32) {
        float t = (tid < (int)(blockDim.x >> 5)) ? sh[tid] : 0.f;
        #pragma unroll
        for (int o = 16; o > 0; o >>= 1) t += __shfl_down_sync(0xffffffffu, t, o);
        if (tid == 0) sh[0] = t;
    }
    __syncthreads();
    float r = sh[0];
    __syncthreads();
    return r;
}
__device__ __forceinline__ float block_max(float v, float* sh) {
    int tid = threadIdx.x;
    #pragma unroll
    for (int o = 16; o > 0; o >>= 1) v = fmaxf(v, __shfl_down_sync(0xffffffffu, v, o));
    if ((tid & 31) == 0) sh[tid >> 5] = v;
    __syncthreads();
    if (tid < 32) {
        float t = (tid < (int)(blockDim.x >> 5)) ? sh[tid] : -INFINITY;
        #pragma unroll
        for (int o = 16; o > 0; o >>= 1) t = fmaxf(t, __shfl_down_sync(0xffffffffu, t, o));
        if (tid == 0) sh[0] = t;
    }
    __syncthreads();
    float r = sh[0];
    __syncthreads();
    return r;
}

// ---------------- LN ----------------
__global__ void __launch_bounds__(256) ln_fused_kernel(
    const float* __restrict__ e1, const float* __restrict__ e2,
    const float* __restrict__ e3, const float* __restrict__ e4,
    const float* __restrict__ lag, const float* __restrict__ lab,
    const float* __restrict__ lcg, const float* __restrict__ lcb,
    __half* __restrict__ cx, __half* __restrict__ ec)
{
    __shared__ float sh[32];
    int token = blockIdx.x;
    int tid = threadIdx.x;
    const float* es[4] = {e1, e2, e3, e4};
    float x[4][2], mg[4], rg[4];
    float stot = 0.f, sstot = 0.f;
    #pragma unroll
    for (int g = 0; g < 4; g++) {
        const float* p = es[g] + (long long)token * E_;
        x[g][0] = p[tid]; x[g][1] = p[tid + 256];
        float s  = block_sum(x[g][0] + x[g][1], sh);
        float ss = block_sum(x[g][0]*x[g][0] + x[g][1]*x[g][1], sh);
        float m = s * (1.f/512.f);
        float v = ss * (1.f/512.f) - m*m;
        mg[g] = m; rg[g] = rsqrtf(v + 1e-6f);
        stot += s; sstot += ss;
    }
    float m = stot * (1.f/2048.f);
    float r = rsqrtf(sstot * (1.f/2048.f) - m*m + 1e-6f);
    #pragma unroll
    for (int g = 0; g < 4; g++) {
        #pragma unroll
        for (int j = 0; j < 2; j++) {
            int e = tid + j*256;
            float xv = x[g][j];
            cx[((long long)g*BN_ + token)*E_ + e] =
                __float2half_rn((xv - mg[g]) * rg[g] * lag[g*E_+e] + lab[g*E_+e]);
            ec[(long long)token*C_ + g*E_ + e] =
                __float2half_rn((xv - m) * r * lcg[g*E_+e] + lcb[g*E_+e]);
        }
    }
}

__global__ void __launch_bounds__(256) ln_rows_kernel(
    const float* __restrict__ X, const float* __restrict__ gamma,
    const float* __restrict__ beta, __half* __restrict__ Y, int rowsPerG)
{
    __shared__ float sh[32];
    long long row = blockIdx.x;
    int tid = threadIdx.x;
    int g = (int)(row / rowsPerG);
    const float* p = X + row * E_;
    float x0 = p[tid], x1 = p[tid+256];
    float s  = block_sum(x0 + x1, sh);
    float ss = block_sum(x0*x0 + x1*x1, sh);
    float m = s * (1.f/512.f);
    float r = rsqrtf(ss * (1.f/512.f) - m*m + 1e-6f);
    __half* q = Y + row * E_;
    q[tid]     = __float2half_rn((x0 - m) * r * gamma[g*E_+tid]     + beta[g*E_+tid]);
    q[tid+256] = __float2half_rn((x1 - m) * r * gamma[g*E_+tid+256] + beta[g*E_+tid+256]);
}

// ---------------- rstd from per-CTA partials ----------------
__global__ void rstd_parts(const float* __restrict__ parts, float* __restrict__ rstd, int nparts) {
    int z = blockIdx.x;
    int t = threadIdx.x;
    float s = 0.f, q = 0.f;
    if (t < nparts) { s = parts[(z*nparts+t)*2]; q = parts[(z*nparts+t)*2+1]; }
    #pragma unroll
    for (int o = 16; o > 0; o >>= 1) {
        s += __shfl_down_sync(0xffffffffu, s, o);
        q += __shfl_down_sync(0xffffffffu, q, o);
    }
    if (t == 0) {
        float m = s * (1.f/(float)ATTZ_);
        rstd[z] = rsqrtf(q * (1.f/(float)ATTZ_) - m*m + 1e-5f);
    }
}

// ---------------- softmax (channel path only) ----------------
template<int NIT, bool PERZ, typename TI>
__global__ void __launch_bounds__(256) softmax_fix(
    const TI* __restrict__ S, __half* __restrict__ O,
    int cols, int ldo, int rowsPerZ,
    const float* __restrict__ rstd, float scale)
{
    __shared__ float sh[32];
    long long row = blockIdx.x;
    const TI* p = S + row * cols;
    __half* q = O + row * ldo;
    float sc = PERZ ? rstd[(int)(row / rowsPerZ)] : scale;
    int tid = threadIdx.x;
    float vals[NIT];
    float mx = -INFINITY;
    #pragma unroll
    for (int it = 0; it < NIT; it++) {
        int i = tid + it*256;
        float t = (i < cols) ? (float)p[i]*sc : -INFINITY;
        vals[it] = t;
        mx = fmaxf(mx, t);
    }
    mx = block_max(mx, sh);
    float s = 0.f;
    #pragma unroll
    for (int it = 0; it < NIT; it++) {
        float e = expf(vals[it] - mx);
        vals[it] = e;
        s += e;
    }
    s = block_sum(s, sh);
    float inv = 1.f / s;
    #pragma unroll
    for (int it = 0; it < NIT; it++) {
        int i = tid + it*256;
        if (i < cols) q[i] = __float2half_rn(vals[it] * inv);
    }
}

// ---------------- tiled transpose ----------------
template<typename TI, typename TO>
__global__ void transpose_t(const TI* __restrict__ in, TO* __restrict__ out,
                            int R, int Cc, int ldo, long long zi, long long zo)
{
    __shared__ float t[32][33];
    const TI* ip = in + (long long)blockIdx.z * zi;
    TO* op = out + (long long)blockIdx.z * zo;
    int c0 = blockIdx.x*32, r0 = blockIdx.y*32;
    int x = threadIdx.x, y = threadIdx.y;
    #pragma unroll
    for (int j = 0; j < 32; j += 8) {
        int r = r0 + y + j, c = c0 + x;
        if (r < R && c < Cc) t[y+j][x] = (float)ip[(long long)r*Cc + c];
    }
    __syncthreads();
    #pragma unroll
    for (int j = 0; j < 32; j += 8) {
        int c = c0 + y + j, r = r0 + x;
        if (r < R && c < Cc) op[(long long)c*ldo + r] = (TO)t[x][y+j];
    }
}

__global__ void transpose4_sq(const float* __restrict__ p0, const float* __restrict__ p1,
                              const float* __restrict__ p2, const float* __restrict__ p3,
                              __half* __restrict__ o0, __half* __restrict__ o1,
                              __half* __restrict__ o2, __half* __restrict__ o3, int D)
{
    __shared__ float t[32][33];
    int zi = blockIdx.z;
    const float* ip = (zi == 0) ? p0 : (zi == 1) ? p1 : (zi == 2) ? p2 : p3;
    __half* op = (zi == 0) ? o0 : (zi == 1) ? o1 : (zi == 2) ? o2 : o3;
    int c0 = blockIdx.x*32, r0 = blockIdx.y*32;
    int x = threadIdx.x, y = threadIdx.y;
    #pragma unroll
    for (int j = 0; j < 32; j += 8) {
        int r = r0 + y + j, c = c0 + x;
        if (r < D && c < D) t[y+j][x] = ip[(long long)r*D + c];
    }
    __syncthreads();
    #pragma unroll
    for (int j = 0; j < 32; j += 8) {
        int c = c0 + y + j, r = r0 + x;
        if (r < D && c < D) op[(long long)c*D + r] = (__half)t[x][y+j];
    }
}

__global__ void kvsT_kernel(const __half* __restrict__ that, __half* __restrict__ kvsT)
{
    __shared__ __half t[32][34];
    int g = blockIdx.z & 3, b = blockIdx.z >> 2;
    int n0 = blockIdx.y*32, e0 = blockIdx.x*32;
    const __half* in = that + (long long)b*N_*C_ + g*E_;
    __half* out = kvsT + (long long)b*E_*FN_ + g*N_;
    int x = threadIdx.x, y = threadIdx.y;
    #pragma unroll
    for (int j = 0; j < 32; j += 8) {
        int n = n0 + y + j;
        if (n < N_) t[y+j][x] = in[(long long)n*C_ + e0 + x];
    }
    __syncthreads();
    #pragma unroll
    for (int j = 0; j < 32; j += 8) {
        int n = n0 + x;
        if (n < N_) out[(long long)(e0+y+j)*FN_ + n] = t[x][y+j];
    }
}

__global__ void merge0_kernel(const __half* __restrict__ cm, __half* __restrict__ ctx0) {
    int idx = blockIdx.x * blockDim.x + threadIdx.x;
    if (idx >= BN_*E_) return;
    int b = idx / NE_;
    int rem = idx % NE_;
    int n = rem / E_;
    int e = rem % E_;
    int h = e >> 6, d = e & 63;
    ctx0[idx] = cm[((long long)(b*H_ + h)*N_ + n)*HD_ + d];
}

__global__ void copy_half8(const __half* __restrict__ src, __half* __restrict__ dst, int n8) {
    int i = blockIdx.x * blockDim.x + threadIdx.x;
    if (i < n8) ((uint4*)dst)[i] = ((const uint4*)src)[i];
}

__global__ void pack_emb(const float* __restrict__ e1, const float* __restrict__ e2,
                         const float* __restrict__ e3, const float* __restrict__ e4,
                         float* __restrict__ out) {
    const float* es[4] = {e1, e2, e3, e4};
    int g = blockIdx.y;
    int i = blockIdx.x * blockDim.x + threadIdx.x;
    if (i < BNE_) out[(long long)g*BNE_ + i] = es[g][i];
}

// ---------------- fp16 mma.sync GEMM (R7 mainloop) + optional fused stats ----------------
__device__ __forceinline__ void epi_store(
    void* __restrict__ Cv, const float* __restrict__ bias, const float* __restrict__ res,
    int ldc, int row, int gc, int M, int act, int outHalf, float alpha, float c0, float c1)
{
    if (row >= M) return;
    float2 v = make_float2(c0*alpha, c1*alpha);
    if (bias) { v.x += bias[gc]; v.y += bias[gc+1]; }
    if (act)  { v.x = gelu_f(v.x); v.y = gelu_f(v.y); }
    if (res)  { float2 rr = *(const float2*)(res + (long long)row*ldc + gc);
                v.x += rr.x; v.y += rr.y; }
    if (outHalf) {
        *(__half2*)((__half*)Cv + (long long)row*ldc + gc) = __floats2half2_rn(v.x, v.y);
    } else {
        *(float2*)((float*)Cv + (long long)row*ldc + gc) = v;
    }
}

template<int TM, int TN, int WM, int WN, int MINB>
__global__ void __launch_bounds__(256, MINB) gemm_h(
    int M, int Ncol, int K,
    const __half* __restrict__ A, int lda,
    const __half* __restrict__ B, int ldb,
    void* __restrict__ Cv, int ldc,
    const float* __restrict__ bias,
    const float* __restrict__ res,
    int act, int outHalf, float alpha,
    int D0, int D1,
    long long sA0, long long sA1, long long sA2,
    long long sB0, long long sB1, long long sB2,
    long long sC0, long long sC1, long long sC2,
    long long sBias0, long long sR0,
    float* __restrict__ sout)
{
    constexpr int WMS = TM / WM;
    constexpr int MI  = WM / 16;
    constexpr int NJ  = WN / 8;
    constexpr int ABUFW = TM * 32;
    constexpr int BBUFW = TN * 32;
    constexpr int ASLOT = (TM*2 + 255) / 256;
    constexpr int BSLOT = (TN*2 + 255) / 256;

    long long z = blockIdx.z;
    int z0 = (int)(z % D0); long long t = z / D0;
    int z1 = (int)(t % D1); int z2 = (int)(t / D1);
    A += z0*sA0 + z1*sA1 + z2*sA2;
    B += z0*sB0 + z1*sB1 + z2*sB2;
    long long coff = z0*sC0 + z1*sC1 + z2*sC2;
    Cv = outHalf ? (void*)((__half*)Cv + coff) : (void*)((float*)Cv + coff);
    if (bias) bias += z0*sBias0;
    if (res)  res  += z0*sR0;

    extern __shared__ uint32_t smw[];
    uint32_t* As = smw;
    uint32_t* Bs = smw + 2*ABUFW;

    int tid = threadIdx.x;
    int lane = tid & 31;
    int wid = tid >> 5;
    int warp_m = wid % WMS;
    int warp_n = wid / WMS;
    int row0 = blockIdx.y * TM;
    int col0 = blockIdx.x * TN;

    float acc[MI][NJ][4];
    #pragma unroll
    for (int i = 0; i < MI; i++)
        #pragma unroll
        for (int j = 0; j < NJ; j++)
            #pragma unroll
            for (int q = 0; q < 4; q++) acc[i][j][q] = 0.f;

    const __half* aPtr[ASLOT]; uint32_t aOff[ASLOT][4]; int aKh[ASLOT]; bool aV[ASLOT];
    const __half* bPtr[BSLOT]; uint32_t bOff[BSLOT][4]; int bKh[BSLOT]; bool bV[BSLOT];
    #pragma unroll
    for (int i = 0; i < ASLOT; i++) {
        int sidx = tid + i*256;
        bool inA = sidx < TM*2;
        int r = inA ? (sidx >> 1) : 0;
        int khw = (sidx & 1) * 16;
        aKh[i] = (sidx & 1) * 32;
        bool val = inA && (row0 + r) < M;
        aV[i] = val;
        aPtr[i] = A + (long long)(val ? row0 + r : 0) * lda;
        int sw = (r & 7) << 2;
        #pragma unroll
        for (int j = 0; j < 4; j++)
            aOff[i][j] = (uint32_t)((r*32 + ((khw + j*4) ^ sw)) << 2);
    }
    #pragma unroll
    for (int i = 0; i < BSLOT; i++) {
        int sidx = tid + i*256;
        bool inB = sidx < TN*2;
        int r = inB ? (sidx >> 1) : 0;
        int khw = (sidx & 1) * 16;
        bKh[i] = (sidx & 1) * 32;
        bool val = inB && (col0 + r) < Ncol;
        bV[i] = val;
        bPtr[i] = B + (long long)(val ? col0 + r : 0) * ldb;
        int sw = (r & 7) << 2;
        #pragma unroll
        for (int j = 0; j < 4; j++)
            bOff[i][j] = (uint32_t)((r*32 + ((khw + j*4) ^ sw)) << 2);
    }

    uint32_t aSm = smem_u32(As);
    uint32_t bSm = smem_u32(Bs);
    int KT = (K + 63) >> 6;
    int lr = lane >> 2;
    int lc = lane & 3;

    // prologue -> buffer 0
    #pragma unroll
    for (int i = 0; i < ASLOT; i++) {
        if ((ASLOT > 1) && (tid + i*256 >= TM*2)) continue;
        #pragma unroll
        for (int j = 0; j < 4; j++) {
            int gk = aKh[i] + j*8;
            int nb = (K - gk) * 2; nb = nb < 0 ? 0 : (nb > 16 ? 16 : nb);
            int ba = aV[i] ? nb : 0;
            cpa16(aSm + aOff[i][j], aPtr[i] + (ba ? gk : 0), ba);
        }
    }
    #pragma unroll
    for (int i = 0; i < BSLOT; i++) {
        if (tid + i*256 >= TN*2) continue;
        #pragma unroll
        for (int j = 0; j < 4; j++) {
            int gk = bKh[i] + j*8;
            int nb = (K - gk) * 2; nb = nb < 0 ? 0 : (nb > 16 ? 16 : nb);
            int bb = bV[i] ? nb : 0;
            cpa16(bSm + bOff[i][j], bPtr[i] + (bb ? gk : 0), bb);
        }
    }
    CP_COMMIT();

    for (int kt = 0; kt < KT; kt++) {
        int p = kt & 1;
        __syncthreads();
        if (kt + 1 < KT) {
            uint32_t aBo = (uint32_t)((1 - p) * ABUFW * 4);
            uint32_t bBo = (uint32_t)((1 - p) * BBUFW * 4);
            int k0 = (kt+1)*64;
            #pragma unroll
            for (int i = 0; i < ASLOT; i++) {
                if ((ASLOT > 1) && (tid + i*256 >= TM*2)) continue;
                #pragma unroll
                for (int j = 0; j < 4; j++) {
                    int gk = k0 + aKh[i] + j*8;
                    int nb = (K - gk) * 2; nb = nb < 0 ? 0 : (nb > 16 ? 16 : nb);
                    int ba = aV[i] ? nb : 0;
                    cpa16(aSm + aBo + aOff[i][j], aPtr[i] + (ba ? gk : 0), ba);
                }
            }
            #pragma unroll
            for (int i = 0; i < BSLOT; i++) {
                if (tid + i*256 >= TN*2) continue;
                #pragma unroll
                for (int j = 0; j < 4; j++) {
                    int gk = k0 + bKh[i] + j*8;
                    int nb = (K - gk) * 2; nb = nb < 0 ? 0 : (nb > 16 ? 16 : nb);
                    int bb = bV[i] ? nb : 0;
                    cpa16(bSm + bBo + bOff[i][j], bPtr[i] + (bb ? gk : 0), bb);
                }
            }
        }
        CP_COMMIT();
        CP_WAIT1();
        __syncthreads();

        const uint32_t* Ab = As + p*ABUFW;
        const uint32_t* Bb = Bs + p*BBUFW;
        #pragma unroll
        for (int ks = 0; ks < 4; ks++) {
            int w0 = ks*8 + lc;
            int w1 = w0 + 4;
            uint32_t af[MI][4], bf[NJ][2];
            #pragma unroll
            for (int i = 0; i < MI; i++) {
                int m = warp_m*WM + i*16 + lr;
                int s = (m & 7) << 2;
                af[i][0] = Ab[m*32 + (w0 ^ s)];
                af[i][1] = Ab[(m+8)*32 + (w0 ^ s)];
                af[i][2] = Ab[m*32 + (w1 ^ s)];
                af[i][3] = Ab[(m+8)*32 + (w1 ^ s)];
            }
            #pragma unroll
            for (int j = 0; j < NJ; j++) {
                int n = warp_n*WN + j*8 + lr;
                int s = (n & 7) << 2;
                bf[j][0] = Bb[n*32 + (w0 ^ s)];
                bf[j][1] = Bb[n*32 + (w1 ^ s)];
            }
            #pragma unroll
            for (int i = 0; i < MI; i++)
                #pragma unroll
                for (int j = 0; j < NJ; j++)
                    mma_f16(acc[i][j], af[i], bf[j]);
        }
    }

    #pragma unroll
    for (int i = 0; i < MI; i++) {
        int gr = row0 + warp_m*WM + i*16 + lr;
        #pragma unroll
        for (int j = 0; j < NJ; j++) {
            int gc = col0 + warp_n*WN + j*8 + lc*2;
            if (gc >= Ncol) continue;
            epi_store(Cv, bias, res, ldc, gr,   gc, M, act, outHalf, alpha, acc[i][j][0], acc[i][j][1]);
            epi_store(Cv, bias, res, ldc, gr+8, gc, M, act, outHalf, alpha, acc[i][j][2], acc[i][j][3]);
        }
    }

    if (sout) {
        float s = 0.f, q = 0.f;
        #pragma unroll
        for (int i = 0; i < MI; i++)
            #pragma unroll
            for (int j = 0; j < NJ; j++)
                #pragma unroll
                for (int qq = 0; qq < 4; qq++) {
                    float v = acc[i][j][qq];
                    s += v; q += v*v;
                }
        #pragma unroll
        for (int o = 16; o > 0; o >>= 1) {
            s += __shfl_down_sync(0xffffffffu, s, o);
            q += __shfl_down_sync(0xffffffffu, q, o);
        }
        float* shf = (float*)smw;
        __syncthreads();
        if (lane == 0) { shf[wid] = s; shf[8 + wid] = q; }
        __syncthreads();
        if (tid == 0) {
            float ts = 0.f, tq = 0.f;
            #pragma unroll
            for (int w = 0; w < 8; w++) { ts += shf[w]; tq += shf[8 + w]; }
            long long cid = (long long)blockIdx.z * (gridDim.x * gridDim.y)
                          + blockIdx.y * gridDim.x + blockIdx.x;
            sout[cid*2]   = ts;
            sout[cid*2+1] = tq;
        }
    }
}

// ---------------- fused softmax+PV: ctx = softmax(rstd*logits) @ V^T ----------------
// TM=128, TN=64, WM=32 (WMS=4), WN=32 (NJ=4) -> 8 warps cover 128x64 exactly.
__global__ void __launch_bounds__(256, 2) ctx_fused(
    int M, int Ncol, int K,
    const __half* __restrict__ A, int lda,
    const __half* __restrict__ B, int ldb,
    __half* __restrict__ Cc, int ldc,
    const float* __restrict__ rstd,
    int D0, int D1,
    long long sA0, long long sA1, long long sA2,
    long long sB0, long long sB1, long long sB2,
    long long sC0, long long sC1, long long sC2)
{
    constexpr int TM = 128, TN = 64, WM = 32;
    constexpr int WMS = 4, MI = 2, NJ = 4;
    constexpr int ABUFW = TM * 32;
    constexpr int BBUFW = TN * 32;

    long long z = blockIdx.z;
    int z0 = (int)(z % D0); long long t = z / D0;
    int z1 = (int)(t % D1); int z2 = (int)(t / D1);
    A += z0*sA0 + z1*sA1 + z2*sA2;
    B += z0*sB0 + z1*sB1 + z2*sB2;
    Cc += z0*sC0 + z1*sC1 + z2*sC2;
    float rs = rstd[blockIdx.z];

    extern __shared__ uint32_t smw[];
    uint32_t* As = smw;
    uint32_t* Bs = smw + 2*ABUFW;

    int tid = threadIdx.x;
    int lane = tid & 31;
    int wid = tid >> 5;
    int warp_m = wid % WMS;
    int warp_n = wid / WMS;
    int row0 = blockIdx.y * TM;
    int col0 = blockIdx.x * TN;

    float acc[MI][NJ][4];
    #pragma unroll
    for (int i = 0; i < MI; i++)
        #pragma unroll
        for (int j = 0; j < NJ; j++)
            #pragma unroll
            for (int q = 0; q < 4; q++) acc[i][j][q] = 0.f;
    float rsum[MI][2];
    #pragma unroll
    for (int i = 0; i < MI; i++) { rsum[i][0] = 0.f; rsum[i][1] = 0.f; }

    int rA = tid >> 1;
    int khwA = (tid & 1) * 16;
    int khA = (tid & 1) * 32;
    bool aV = (row0 + rA) < M;
    const __half* aPtr = A + (long long)(aV ? row0 + rA : 0) * lda;
    uint32_t aOff[4];
    {
        int sw = (rA & 7) << 2;
        #pragma unroll
        for (int j = 0; j < 4; j++)
            aOff[j] = (uint32_t)((rA*32 + ((khwA + j*4) ^ sw)) << 2);
    }
    bool inB = tid < TN*2;
    int rB = inB ? (tid >> 1) : 0;
    int khwB = (tid & 1) * 16;
    int khB = (tid & 1) * 32;
    bool bV = inB && (col0 + rB) < Ncol;
    const __half* bPtr = B + (long long)(bV ? col0 + rB : 0) * ldb;
    uint32_t bOff[4];
    {
        int sw = (rB & 7) << 2;
        #pragma unroll
        for (int j = 0; j < 4; j++)
            bOff[j] = (uint32_t)((rB*32 + ((khwB + j*4) ^ sw)) << 2);
    }

    uint32_t aSm = smem_u32(As);
    uint32_t bSm = smem_u32(Bs);
    int KT = (K + 63) >> 6;
    int lr = lane >> 2;
    int lc = lane & 3;

    // prologue
    #pragma unroll
    for (int j = 0; j < 4; j++) {
        int gk = khA + j*8;
        int nb = (K - gk) * 2; nb = nb < 0 ? 0 : (nb > 16 ? 16 : nb);
        int ba = aV ? nb : 0;
        cpa16(aSm + aOff[j], aPtr + (ba ? gk : 0), ba);
    }
    if (inB) {
        #pragma unroll
        for (int j = 0; j < 4; j++) {
            int gk = khB + j*8;
            int nb = (K - gk) * 2; nb = nb < 0 ? 0 : (nb > 16 ? 16 : nb);
            int bb = bV ? nb : 0;
            cpa16(bSm + bOff[j], bPtr + (bb ? gk : 0), bb);
        }
    }
    CP_COMMIT();

    for (int kt = 0; kt < KT; kt++) {
        int p = kt & 1;
        __syncthreads();
        if (kt + 1 < KT) {
            uint32_t aBo = (uint32_t)((1 - p) * ABUFW * 4);
            uint32_t bBo = (uint32_t)((1 - p) * BBUFW * 4);
            int k0 = (kt+1)*64;
            #pragma unroll
            for (int j = 0; j < 4; j++) {
                int gk = k0 + khA + j*8;
                int nb = (K - gk) * 2; nb = nb < 0 ? 0 : (nb > 16 ? 16 : nb);
                int ba = aV ? nb : 0;
                cpa16(aSm + aBo + aOff[j], aPtr + (ba ? gk : 0), ba);
            }
            if (inB) {
                #pragma unroll
                for (int j = 0; j < 4; j++) {
                    int gk = k0 + khB + j*8;
                    int nb = (K - gk) * 2; nb = nb < 0 ? 0 : (nb > 16 ? 16 : nb);
                    int bb = bV ? nb : 0;
                    cpa16(bSm + bBo + bOff[j], bPtr + (bb ? gk : 0), bb);
                }
            }
        }
        CP_COMMIT();
        CP_WAIT1();
        __syncthreads();

        const uint32_t* Ab = As + p*ABUFW;
        const uint32_t* Bb = Bs + p*BBUFW;
        #pragma unroll
        for (int ks = 0; ks < 4; ks++) {
            int w0 = ks*8 + lc;
            int w1 = w0 + 4;
            int kb = kt*64 + ks*16 + lc*2;
            bool v0 = kb < K;
            bool v1 = kb + 8 < K;
            uint32_t af[MI][4], bf[NJ][2];
            #pragma unroll
            for (int i = 0; i < MI; i++) {
                int m = warp_m*WM + i*16 + lr;
                int s = (m & 7) << 2;
                af[i][0] = exp_h2(Ab[m*32 + (w0 ^ s)],     rs, v0, rsum[i][0]);
                af[i][1] = exp_h2(Ab[(m+8)*32 + (w0 ^ s)], rs, v0, rsum[i][1]);
                af[i][2] = exp_h2(Ab[m*32 + (w1 ^ s)],     rs, v1, rsum[i][0]);
                af[i][3] = exp_h2(Ab[(m+8)*32 + (w1 ^ s)], rs, v1, rsum[i][1]);
            }
            #pragma unroll
            for (int j = 0; j < NJ; j++) {
                int n = warp_n*32 + j*8 + lr;
                int s = (n & 7) << 2;
                bf[j][0] = Bb[n*32 + (w0 ^ s)];
                bf[j][1] = Bb[n*32 + (w1 ^ s)];
            }
            #pragma unroll
            for (int i = 0; i < MI; i++)
                #pragma unroll
                for (int j = 0; j < NJ; j++)
                    mma_f16(acc[i][j], af[i], bf[j]);
        }
    }

    // epilogue: reduce rowsums across lc lanes, normalize, store
    #pragma unroll
    for (int i = 0; i < MI; i++) {
        float s0 = rsum[i][0], s1 = rsum[i][1];
        s0 += __shfl_xor_sync(0xffffffffu, s0, 1);
        s0 += __shfl_xor_sync(0xffffffffu, s0, 2);
        s1 += __shfl_xor_sync(0xffffffffu, s1, 1);
        s1 += __shfl_xor_sync(0xffffffffu, s1, 2);
        float i0 = 1.f / s0, i1 = 1.f / s1;
        int gr = row0 + warp_m*WM + i*16 + lr;
        #pragma unroll
        for (int j = 0; j < NJ; j++) {
            int gc = col0 + warp_n*32 + j*8 + lc*2;
            if (gc >= Ncol) continue;
            if (gr < M)
                *(__half2*)(Cc + (long long)gr*ldc + gc) =
                    __floats2half2_rn(acc[i][j][0]*i0, acc[i][j][1]*i0);
            if (gr + 8 < M)
                *(__half2*)(Cc + (long long)(gr+8)*ldc + gc) =
                    __floats2half2_rn(acc[i][j][2]*i1, acc[i][j][3]*i1);
        }
    }
}

// ---------------- host ----------------
static void* symaddr(const void* sym) {
    void* p = nullptr;
    cudaGetSymbolAddress(&p, sym);
    return p;
}

#define G1 gemm_h<128,128,64,32,2>
#define SM1 65536
#define SM3 49152

extern "C" void kernel_launch(void* const* d_in, const int* in_sizes, int n_in,
                              void* d_out, int out_size) {
    const float* emb[4] = {(const float*)d_in[0], (const float*)d_in[1],
                           (const float*)d_in[2], (const float*)d_in[3]};
    const float* lag  = (const float*)d_in[4];
    const float* lab  = (const float*)d_in[5];
    const float* lcg  = (const float*)d_in[6];
    const float* lcb  = (const float*)d_in[7];
    const float* Wq   = (const float*)d_in[8];
    const float* Wk   = (const float*)d_in[9];
    const float* Wv   = (const float*)d_in[10];
    const float* Wo   = (const float*)d_in[11];
    const float* q_w  = (const float*)d_in[12];
    const float* k_w  = (const float*)d_in[13];
    const float* v_w  = (const float*)d_in[14];
    const float* outw = (const float*)d_in[15];
    const float* lfg  = (const float*)d_in[16];
    const float* lfb  = (const float*)d_in[17];
    const float* fc1w = (const float*)d_in[18];
    const float* fc1b = (const float*)d_in[19];
    const float* fc2w = (const float*)d_in[20];
    const float* fc2b = (const float*)d_in[21];
    float* out = (float*)d_out;

    cudaFuncSetAttribute(G1, cudaFuncAttributeMaxDynamicSharedMemorySize, SM1);
    cudaFuncSetAttribute(ctx_fused, cudaFuncAttributeMaxDynamicSharedMemorySize, SM3);

    __half* cx   = (__half*)symaddr(h_cx);   __half* cxT  = (__half*)symaddr(h_cxT);
    __half* ec   = (__half*)symaddr(h_ec);
    __half* qkv  = (__half*)symaddr(h_qkv);  __half* vcT  = (__half*)symaddr(h_vcT);
    float*  sch  = (float*)symaddr(g_sch);   __half* schh = (__half*)symaddr(h_sch);
    __half* tbuf = (__half*)symaddr(h_t);    __half* that = (__half*)symaddr(h_that);
    __half* kvsT = (__half*)symaddr(h_kvsT);
    __half* KV   = (__half*)symaddr(h_KV);   __half* VT   = (__half*)symaddr(h_VT);
    __half* Qb   = (__half*)symaddr(h_Q);
    __half* attnL= (__half*)symaddr(h_attnL);
    float*  parts= (float*)symaddr(g_parts); float*  rstdp= (float*)symaddr(g_rstd);
    __half* cm   = (__half*)symaddr(h_cm);   __half* ctx0 = (__half*)symaddr(h_ctx0);
    float*  embA = (float*)symaddr(g_embA);
    float*  hbuf = (float*)symaddr(g_h);     __half* xln  = (__half*)symaddr(h_xln);
    __half* x1   = (__half*)symaddr(h_x1);
    __half* qwT  = (__half*)symaddr(h_qwT);  __half* kvwT = (__half*)symaddr(h_kvwT);
    __half* Wqkv = (__half*)symaddr(h_Wqkv); __half* WoT  = (__half*)symaddr(h_WoT);
    __half* outwT= (__half*)symaddr(h_outwT);
    __half* fc1wT= (__half*)symaddr(h_fc1wT);__half* fc2wT= (__half*)symaddr(h_fc2wT);

    const long long Z = 0;
    dim3 tb(32, 8);

    // 1. fused LayerNorms + emb pack
    ln_fused_kernel<<<BN_, 256>>>(emb[0], emb[1], emb[2], emb[3], lag, lab, lcg, lcb, cx, ec);
    pack_emb<<<dim3((BNE_+255)/256, 4), 256>>>(emb[0], emb[1], emb[2], emb[3], embA);

    // 2. weight transposes
    transpose4_sq<<<dim3(64,64,4), tb>>>(Wq, Wk, Wv, Wo,
                                         Wqkv, Wqkv + (long long)C_*C_, Wqkv + 2LL*C_*C_, WoT, C_);
    transpose4_sq<<<dim3(25,25,2), tb>>>(k_w, v_w, k_w, k_w,
                                         kvwT, kvwT + (long long)FN_*FN_, kvwT, kvwT, FN_);
    transpose_t<float,__half><<<dim3(7,7,4),   tb>>>(q_w, qwT, N_, N_, LP_, (long long)N_*N_, (long long)N_*LP_);
    transpose_t<float,__half><<<dim3(16,16,4), tb>>>(outw, outwT, E_, E_, E_, (long long)E_*E_, (long long)E_*E_);
    transpose_t<float,__half><<<dim3(64,16,4), tb>>>(fc1w, fc1wT, E_, 2048, E_, (long long)E_*2048, (long long)2048*E_);
    transpose_t<float,__half><<<dim3(16,64,4), tb>>>(fc2w, fc2wT, 2048, E_, 2048, (long long)2048*E_, (long long)E_*2048);
    transpose_t<__half,__half><<<dim3(16,7,64), tb>>>(cx, cxT, N_, E_, LP_, (long long)NE_, (long long)E_*LP_);

    // 3. channel projections merged QKV: G1 @2CTA
    {
        dim3 g(16, 25, 3);
        G1<<<g,256,SM1>>>(BN_, C_, C_, ec, C_, Wqkv, C_, qkv, C_, nullptr, nullptr, 0, 1, 1.f,
                          3, 1,
                          Z, Z, Z,
                          (long long)C_*C_, Z, Z,
                          (long long)BN_*C_, Z, Z,
                          Z, Z, nullptr);
    }
    transpose_t<__half,__half><<<dim3(64,7,16), tb>>>(qkv + 2LL*BN_*C_, vcT, N_, C_, LP_,
                                                      (long long)N_*C_, (long long)C_*LP_);

    // 4. channel scores per (h,b): fp32 logits (G1 @2CTA)
    {
        dim3 g(2, 2, B_*H_);
        G1<<<g,256,SM1>>>(N_, N_, HDC_, qkv, C_, qkv + (long long)BN_*C_, C_, sch, N_,
                          nullptr, nullptr, 0, 0, 0.0625f,
                          H_, B_,
                          256LL, (long long)N_*C_, Z,
                          256LL, (long long)N_*C_, Z,
                          (long long)SCHZ_, (long long)H_*SCHZ_, Z,
                          Z, Z, nullptr);
    }
    // 5. channel softmax -> half probs
    softmax_fix<1,false,float><<<B_*H_*N_, 256>>>(sch, schh, N_, LP_, 1, nullptr, 1.f);

    // 6. T = s @ v per (h,b): G1 @2CTA
    {
        dim3 g(2, 2, B_*H_);
        G1<<<g,256,SM1>>>(N_, HDC_, N_, schh, LP_, vcT, LP_, tbuf, C_, nullptr, nullptr, 0, 1, 1.f,
                          H_, B_,
                          (long long)N_*LP_, (long long)H_*N_*LP_, Z,
                          (long long)256*LP_, (long long)C_*LP_, Z,
                          256LL, (long long)N_*C_, Z,
                          Z, Z, nullptr);
    }
    // 7. T_hat = T @ Wo: G1 @2CTA
    {
        dim3 g(16, 25, 1);
        G1<<<g,256,SM1>>>(BN_, C_, C_, tbuf, C_, WoT, C_, that, C_, nullptr, nullptr, 0, 1, 1.f,
                          1,1, Z,Z,Z, Z,Z,Z, Z,Z,Z, Z,Z, nullptr);
    }
    // 8. fused KV_S reshape + transpose
    kvsT_kernel<<<dim3(16, 7, 64), tb>>>(that, kvsT);

    // 9. K/V token-mix merged: G1 @2CTA
    {
        dim3 g(4, 7, 2*B_);
        G1<<<g,256,SM1>>>(FN_, E_, FN_, kvwT, FN_, kvsT, FN_, KV, E_, nullptr, nullptr, 0, 1, 1.f,
                          2, B_,
                          (long long)FN_*FN_, Z, Z,
                          Z, (long long)E_*FN_, Z,
                          (long long)B_*FNE_, (long long)FNE_, Z,
                          Z, Z, nullptr);
    }
    transpose_t<__half,__half><<<dim3(16,25,16), tb>>>(KV + (long long)B_*FNE_, VT, FN_, E_, FN_,
                                                       (long long)FNE_, (long long)E_*FN_);

    // 10. Q token-mix per (b,g): G1 @2CTA
    {
        dim3 g(4, 2, 4*B_);
        G1<<<g,256,SM1>>>(N_, E_, N_, qwT, LP_, cxT, LP_, Qb, E_, nullptr, nullptr, 0, 1, 1.f,
                          B_, 4,
                          Z, (long long)N_*LP_, Z,
                          (long long)E_*LP_, (long long)B_*E_*LP_, Z,
                          (long long)NE_, (long long)BNE_, Z,
                          Z, Z, nullptr);
    }
    // 11. spatial logits per (h,b,g): HALF logits + fused fp32 stats partials (G1 @2CTA)
    {
        dim3 g(7, 2, 512);
        G1<<<g,256,SM1>>>(N_, FN_, HD_, Qb, E_, KV, E_, attnL, FN_, nullptr, nullptr, 0, 1, 1.f,
                          H_, B_,
                          64LL, (long long)NE_,  (long long)BNE_,
                          64LL, (long long)FNE_, Z,
                          (long long)ATTZ_, (long long)H_*ATTZ_, (long long)B_*H_*ATTZ_,
                          Z, Z, parts);
    }
    // 12. rstd from partials
    rstd_parts<<<512, 32>>>(parts, rstdp, 14);

    // 13+14 fused: ctx = softmax(rstd*logits) @ Vh per (h,b,g) -> cm
    {
        dim3 g(1, 2, 512);
        ctx_fused<<<g,256,SM3>>>(N_, HD_, FN_, attnL, FN_, VT, FN_, cm, HD_, rstdp,
                          H_, B_,
                          (long long)ATTZ_, (long long)H_*ATTZ_, (long long)B_*H_*ATTZ_,
                          (long long)HD_*FN_, (long long)E_*FN_, Z,
                          (long long)N_*HD_, (long long)H_*N_*HD_, (long long)BNE_);
    }
    // 15. branch-0 head permute -> slot 0
    merge0_kernel<<<(BN_*E_ + 255)/256, 256>>>(cm, ctx0);
    copy_half8<<<(BNE_/8 + 255)/256, 256>>>(ctx0, cm, BNE_/8);

    // 16. out projection + residual-1 merged over g: G1 @2CTA
    {
        dim3 g(4, 25, 4);
        G1<<<g,256,SM1>>>(BN_, E_, E_, cm, E_, outwT, E_, hbuf, E_,
                          nullptr, embA, 0, 0, 1.f,
                          4, 1,
                          (long long)BNE_, Z, Z,
                          (long long)E_*E_, Z, Z,
                          (long long)BNE_, Z, Z,
                          Z, (long long)BNE_, nullptr);
    }
    // 17. FFN LayerNorm
    ln_rows_kernel<<<4*BN_, 256>>>(hbuf, lfg, lfb, xln, BN_);

    // 18. fc1 + bias + GELU per g: G1 @2CTA
    {
        dim3 g(16, 25, 4);
        G1<<<g,256,SM1>>>(BN_, 4*E_, E_, xln, E_, fc1wT, E_, x1, 4*E_,
                          fc1b, nullptr, 1, 1, 1.f,
                          4, 1,
                          (long long)BNE_, Z, Z,
                          (long long)2048*E_, Z, Z,
                          (long long)BN_*2048, Z, Z,
                          (long long)2048, Z, nullptr);
    }
    // 19. fc2 + bias + residual-2 -> out: G1 @2CTA
    {
        dim3 g(4, 25, 4);
        G1<<<g,256,SM1>>>(BN_, E_, 4*E_, x1, 4*E_, fc2wT, 4*E_, out, E_,
                          fc2b, hbuf, 0, 0, 1.f,
                          4, 1,
                          (long long)BN_*2048, Z, Z,
                          (long long)E_*2048, Z, Z,
                          (long long)BNE_, Z, Z,
                          (long long)E_, (long long)BNE_, nullptr);
    }
}